// round 4
// baseline (speedup 1.0000x reference)
#include <cuda_runtime.h>
#include <cuda_bf16.h>
#include <math.h>
#include <cstdint>

// Problem constants
#define BB 8
#define HH 37
#define WW 37
#define NN (HH * WW)          // 1369
#define CC 1024
#define MM (BB * NN)          // 10952
#define NHEADS 8
#define HD 128
#define NPTS 8
#define K3 3072               // split-K: A=[Ah|Al|Ah], B=[Bh|Bh|Bl]
#define NCHUNK (K3 / 64)      // 48
#define STAGES 3
#define STAGE_BYTES 49152     // A 16K + B 32K
#define SMEM_SZ (STAGES * STAGE_BYTES)

// ---------------------------------------------------------------------------
// Scratch
// ---------------------------------------------------------------------------
__device__ __nv_bfloat16 g_abig[MM * K3];
__device__ __nv_bfloat16 g_bop_q[CC * K3];
__device__ __nv_bfloat16 g_bop_k[CC * K3];
__device__ __nv_bfloat16 g_bop_o[CC * K3];
__device__ __nv_bfloat16 g_bop_f[256 * K3];   // padded to 256 rows
__device__ float g_q[MM * CC];
__device__ float g_k[MM * CC];
__device__ float g_offp[MM * 128];

// ---------------------------------------------------------------------------
__device__ __forceinline__ uint32_t smem_u32(const void* p) {
    uint32_t a;
    asm("{ .reg .u64 t; cvta.to.shared.u64 t, %1; cvt.u32.u64 %0, t; }" : "=r"(a) : "l"(p));
    return a;
}
__device__ __forceinline__ void cp16(uint32_t dst, const void* src, bool valid) {
    int sz = valid ? 16 : 0;
    asm volatile("cp.async.cg.shared.global [%0], [%1], 16, %2;"
                 :: "r"(dst), "l"(src), "r"(sz) : "memory");
}
#define CP_COMMIT() asm volatile("cp.async.commit_group;" ::: "memory")
#define CP_WAIT1()  asm volatile("cp.async.wait_group 1;" ::: "memory")

__device__ __forceinline__ void ldsm4(uint32_t* r, uint32_t addr) {
    asm volatile("ldmatrix.sync.aligned.m8n8.x4.shared.b16 {%0,%1,%2,%3}, [%4];"
                 : "=r"(r[0]), "=r"(r[1]), "=r"(r[2]), "=r"(r[3]) : "r"(addr));
}
__device__ __forceinline__ void mma16816(float* c, const uint32_t* a, const uint32_t* b) {
    asm volatile(
        "mma.sync.aligned.m16n8k16.row.col.f32.bf16.bf16.f32 "
        "{%0,%1,%2,%3},{%4,%5,%6,%7},{%8,%9},{%0,%1,%2,%3};"
        : "+f"(c[0]), "+f"(c[1]), "+f"(c[2]), "+f"(c[3])
        : "r"(a[0]), "r"(a[1]), "r"(a[2]), "r"(a[3]), "r"(b[0]), "r"(b[1]));
}

// ---------------------------------------------------------------------------
// bf16 HMMA GEMM: C[M x 256-tile] = A[M,3072] x Bop[n][3072]^T + bias
// CTA 128x256, 512 threads, 16 warps (4m x 4n), warp tile 32x64.
// 3-stage cp.async pipeline, K-chunk 64. ncols guards epilogue for narrow C.
// ---------------------------------------------------------------------------
__global__ __launch_bounds__(512, 1)
void gemm_hmma(const __nv_bfloat16* __restrict__ A, const __nv_bfloat16* __restrict__ B,
               const float* __restrict__ bias, float* __restrict__ C,
               int M, int ldc, int ncols) {
    extern __shared__ char smem[];
    const uint32_t sb0 = smem_u32(smem);
    const int tid = threadIdx.x, wid = tid >> 5, lane = tid & 31;
    const int m0 = blockIdx.y * 128;
    const int col0 = blockIdx.x * 256;
    const __nv_bfloat16* Bc0 = B + (size_t)col0 * K3;

    auto load_stage = [&](int ck, int stage) {
        const uint32_t sa = sb0 + stage * STAGE_BYTES;
        const __nv_bfloat16* Ac = A + ck * 64;
        const __nv_bfloat16* Bc = Bc0 + ck * 64;
#pragma unroll
        for (int i = 0; i < 2; i++) {           // A: 128 rows x 8 c16
            int id = tid + i * 512;
            int row = id >> 3, c16 = id & 7;
            int gr = m0 + row;
            bool v = gr < M;
            int grc = v ? gr : (M - 1);
            uint32_t dst = sa + row * 128 + (((uint32_t)c16 ^ (row & 7)) << 4);
            cp16(dst, Ac + (size_t)grc * K3 + c16 * 8, v);
        }
#pragma unroll
        for (int i = 0; i < 4; i++) {           // B: 256 rows x 8 c16
            int id = tid + i * 512;
            int row = id >> 3, c16 = id & 7;
            uint32_t dst = sa + 16384 + row * 128 + (((uint32_t)c16 ^ (row & 7)) << 4);
            cp16(dst, Bc + (size_t)row * K3 + c16 * 8, true);
        }
        CP_COMMIT();
    };

    float acc[2][8][4];
#pragma unroll
    for (int mt = 0; mt < 2; mt++)
#pragma unroll
        for (int nt = 0; nt < 8; nt++)
#pragma unroll
            for (int j = 0; j < 4; j++) acc[mt][nt][j] = 0.0f;

    load_stage(0, 0);
    load_stage(1, 1);

    const int wm = (wid & 3) * 32;      // 4 m-groups
    const int wn = (wid >> 2) * 64;     // 4 n-groups

    for (int c = 0; c < NCHUNK; c++) {
        CP_WAIT1();
        __syncthreads();
        if (c + 2 < NCHUNK) load_stage(c + 2, (c + 2) % STAGES);
        else CP_COMMIT();

        const uint32_t sa = sb0 + (c % STAGES) * STAGE_BYTES;
        const uint32_t sbB = sa + 16384;

#pragma unroll
        for (int ks = 0; ks < 4; ks++) {
            uint32_t af[2][4];
#pragma unroll
            for (int mt = 0; mt < 2; mt++) {
                int row = wm + mt * 16 + (lane & 15);
                uint32_t c16 = (uint32_t)(ks * 2 + (lane >> 4)) ^ (row & 7);
                ldsm4(af[mt], sa + row * 128 + (c16 << 4));
            }
            uint32_t bf[8][2];
#pragma unroll
            for (int nt2 = 0; nt2 < 4; nt2++) {
                int group = lane >> 3;
                int nrow = wn + nt2 * 16 + (group >> 1) * 8 + (lane & 7);
                uint32_t c16 = (uint32_t)(ks * 2 + (group & 1)) ^ (nrow & 7);
                uint32_t r[4];
                ldsm4(r, sbB + nrow * 128 + (c16 << 4));
                bf[nt2 * 2][0] = r[0]; bf[nt2 * 2][1] = r[1];
                bf[nt2 * 2 + 1][0] = r[2]; bf[nt2 * 2 + 1][1] = r[3];
            }
#pragma unroll
            for (int mt = 0; mt < 2; mt++)
#pragma unroll
                for (int nt = 0; nt < 8; nt++)
                    mma16816(acc[mt][nt], af[mt], bf[nt]);
        }
        __syncthreads();
    }

    // epilogue
    const int lr = lane >> 2, lc = (lane & 3) * 2;
#pragma unroll
    for (int mt = 0; mt < 2; mt++) {
#pragma unroll
        for (int nt = 0; nt < 8; nt++) {
            int cb = col0 + wn + nt * 8 + lc;
            if (cb >= ncols) continue;
            int r0 = m0 + wm + mt * 16 + lr;
            float b0 = bias[cb], b1 = bias[cb + 1];
            if (r0 < M) {
                float2 v = make_float2(acc[mt][nt][0] + b0, acc[mt][nt][1] + b1);
                *reinterpret_cast<float2*>(C + (size_t)r0 * ldc + cb) = v;
            }
            int r1 = r0 + 8;
            if (r1 < M) {
                float2 v = make_float2(acc[mt][nt][2] + b0, acc[mt][nt][3] + b1);
                *reinterpret_cast<float2*>(C + (size_t)r1 * ldc + cb) = v;
            }
        }
    }
}

// ---------------------------------------------------------------------------
// Activation conversion: fp32 [M][1024] -> bf16 [M][3072] as [hi | lo | hi]
// ---------------------------------------------------------------------------
__global__ __launch_bounds__(256)
void conv_act(const float* __restrict__ A, __nv_bfloat16* __restrict__ out) {
    size_t i = (size_t)blockIdx.x * blockDim.x + threadIdx.x;
    if (i >= (size_t)MM * 128) return;
    size_t r = i >> 7;
    int c8 = (int)(i & 127) * 8;
    const float4* p = reinterpret_cast<const float4*>(A + r * CC + c8);
    float4 v0 = p[0], v1 = p[1];
    float vv[8] = {v0.x, v0.y, v0.z, v0.w, v1.x, v1.y, v1.z, v1.w};
    __nv_bfloat16 hi[8], lo[8];
#pragma unroll
    for (int j = 0; j < 8; j++) {
        hi[j] = __float2bfloat16(vv[j]);
        lo[j] = __float2bfloat16(vv[j] - __bfloat162float(hi[j]));
    }
    __nv_bfloat16* rp = out + r * K3;
    *reinterpret_cast<uint4*>(rp + c8)        = *reinterpret_cast<uint4*>(hi);
    *reinterpret_cast<uint4*>(rp + c8 + 1024) = *reinterpret_cast<uint4*>(lo);
    *reinterpret_cast<uint4*>(rp + c8 + 2048) = *reinterpret_cast<uint4*>(hi);
}

// ---------------------------------------------------------------------------
// Weight conversion (transpose): W[1024][ldw] cols [0,nvalid) ->
// Bop[n][3072] = [hi | hi | lo]; rows n >= nvalid get zeros.
// ---------------------------------------------------------------------------
__global__ __launch_bounds__(256)
void conv_w(const float* __restrict__ W, int ldw, int nvalid, __nv_bfloat16* __restrict__ Bop) {
    __shared__ float t[32][33];
    const int n0 = blockIdx.x * 32, k0 = blockIdx.y * 32;
    const int tx = threadIdx.x, ty = threadIdx.y;
#pragma unroll
    for (int j = ty; j < 32; j += 8) {
        int n = n0 + tx, k = k0 + j;
        t[j][tx] = (n < nvalid) ? W[(size_t)k * ldw + n] : 0.0f;
    }
    __syncthreads();
#pragma unroll
    for (int j = ty; j < 32; j += 8) {
        int n = n0 + j, k = k0 + tx;
        float v = t[tx][j];
        __nv_bfloat16 h = __float2bfloat16(v);
        __nv_bfloat16 l = __float2bfloat16(v - __bfloat162float(h));
        __nv_bfloat16* row = Bop + (size_t)n * K3;
        row[k] = h; row[k + 1024] = h; row[k + 2048] = l;
    }
}

// ---------------------------------------------------------------------------
// Sampling + attention. One warp per (b, n, head). off stride = 128.
// Writes the bf16 split operand [hi|lo|hi] directly (feeds the final GEMM).
// ---------------------------------------------------------------------------
__global__ __launch_bounds__(256)
void sample_attn_kernel(const float* __restrict__ q, const float* __restrict__ k,
                        const float* __restrict__ off, __nv_bfloat16* __restrict__ outop) {
    const int gwarp = (blockIdx.x * blockDim.x + threadIdx.x) >> 5;
    const int lane = threadIdx.x & 31;
    if (gwarp >= MM * NHEADS) return;

    const int h = gwarp & (NHEADS - 1);
    const int m = gwarp >> 3;
    const int n = m % NN;
    const int b = m / NN;

    const int ch = h * HD + lane * 4;
    float4 qv = *reinterpret_cast<const float4*>(q + (size_t)m * CC + ch);

    const int iy_n = n / WW;
    const int ix_n = n % WW;
    const float cy = -1.0f + 2.0f * (float)iy_n / (float)(HH - 1);
    const float cx = -1.0f + 2.0f * (float)ix_n / (float)(WW - 1);

    const float* offp = off + (size_t)m * 128 + h * (NPTS * 2);
    const float* kb = k + (size_t)b * NN * CC;

    float sk[NPTS][4];
    float score[NPTS];
    const float scale = 0.08838834764831845f;

#pragma unroll
    for (int p = 0; p < NPTS; p++) {
        float l0 = cy + offp[2 * p + 0];
        float l1 = cx + offp[2 * p + 1];
        float ix = (l0 + 1.0f) * 0.5f * (float)(WW - 1);
        float iy = (l1 + 1.0f) * 0.5f * (float)(HH - 1);
        ix = fminf(fmaxf(ix, 0.0f), (float)(WW - 1));
        iy = fminf(fmaxf(iy, 0.0f), (float)(HH - 1));
        float x0f = floorf(ix), y0f = floorf(iy);
        float wx = ix - x0f, wy = iy - y0f;
        int x0 = (int)x0f, y0 = (int)y0f;
        int x1 = min(x0 + 1, WW - 1);
        int y1 = min(y0 + 1, HH - 1);

        const float4 g00 = *reinterpret_cast<const float4*>(kb + (size_t)(y0 * WW + x0) * CC + ch);
        const float4 g01 = *reinterpret_cast<const float4*>(kb + (size_t)(y0 * WW + x1) * CC + ch);
        const float4 g10 = *reinterpret_cast<const float4*>(kb + (size_t)(y1 * WW + x0) * CC + ch);
        const float4 g11 = *reinterpret_cast<const float4*>(kb + (size_t)(y1 * WW + x1) * CC + ch);

        float w00 = (1.0f - wy) * (1.0f - wx);
        float w01 = (1.0f - wy) * wx;
        float w10 = wy * (1.0f - wx);
        float w11 = wy * wx;

        sk[p][0] = g00.x * w00 + g01.x * w01 + g10.x * w10 + g11.x * w11;
        sk[p][1] = g00.y * w00 + g01.y * w01 + g10.y * w10 + g11.y * w11;
        sk[p][2] = g00.z * w00 + g01.z * w01 + g10.z * w10 + g11.z * w11;
        sk[p][3] = g00.w * w00 + g01.w * w01 + g10.w * w10 + g11.w * w11;

        float s = qv.x * sk[p][0] + qv.y * sk[p][1] + qv.z * sk[p][2] + qv.w * sk[p][3];
#pragma unroll
        for (int d = 16; d > 0; d >>= 1)
            s += __shfl_xor_sync(0xFFFFFFFFu, s, d);
        score[p] = s * scale;
    }

    float mx = score[0];
#pragma unroll
    for (int p = 1; p < NPTS; p++) mx = fmaxf(mx, score[p]);
    float denom = 0.0f;
    float e[NPTS];
#pragma unroll
    for (int p = 0; p < NPTS; p++) { e[p] = expf(score[p] - mx); denom += e[p]; }
    float inv = 1.0f / denom;

    float av[4] = {0.f, 0.f, 0.f, 0.f};
#pragma unroll
    for (int p = 0; p < NPTS; p++) {
        float a = e[p] * inv;
        av[0] += a * sk[p][0];
        av[1] += a * sk[p][1];
        av[2] += a * sk[p][2];
        av[3] += a * sk[p][3];
    }

    // write bf16 split operand directly: [hi | lo | hi]
    __nv_bfloat16 hi[4], lo[4];
#pragma unroll
    for (int j = 0; j < 4; j++) {
        hi[j] = __float2bfloat16(av[j]);
        lo[j] = __float2bfloat16(av[j] - __bfloat162float(hi[j]));
    }
    __nv_bfloat16* rp = outop + (size_t)m * K3;
    *reinterpret_cast<uint2*>(rp + ch)        = *reinterpret_cast<uint2*>(hi);
    *reinterpret_cast<uint2*>(rp + ch + 1024) = *reinterpret_cast<uint2*>(lo);
    *reinterpret_cast<uint2*>(rp + ch + 2048) = *reinterpret_cast<uint2*>(hi);
}

// ---------------------------------------------------------------------------
extern "C" void kernel_launch(void* const* d_in, const int* in_sizes, int n_in,
                              void* d_out, int out_size) {
    const float* query = (const float*)d_in[0];
    const float* ref   = (const float*)d_in[1];
    const float* Wq    = (const float*)d_in[2];
    const float* bq    = (const float*)d_in[3];
    const float* Wkv   = (const float*)d_in[4];
    const float* bkv   = (const float*)d_in[5];
    const float* Woff  = (const float*)d_in[6];
    const float* boff  = (const float*)d_in[7];
    const float* Wout  = (const float*)d_in[8];
    const float* bout  = (const float*)d_in[9];
    float* outp = (float*)d_out;

    __nv_bfloat16 *abig, *bq_op, *bk_op, *bo_op, *bf_op;
    float *qb, *kb, *offp;
    cudaGetSymbolAddress((void**)&abig,  g_abig);
    cudaGetSymbolAddress((void**)&bq_op, g_bop_q);
    cudaGetSymbolAddress((void**)&bk_op, g_bop_k);
    cudaGetSymbolAddress((void**)&bo_op, g_bop_o);
    cudaGetSymbolAddress((void**)&bf_op, g_bop_f);
    cudaGetSymbolAddress((void**)&qb,    g_q);
    cudaGetSymbolAddress((void**)&kb,    g_k);
    cudaGetSymbolAddress((void**)&offp,  g_offp);

    cudaFuncSetAttribute(gemm_hmma, cudaFuncAttributeMaxDynamicSharedMemorySize, SMEM_SZ);

    const int mtiles = (MM + 127) / 128;  // 86
    dim3 wblk(32, 8);

    // weight conversions
    conv_w<<<dim3(32, 32), wblk>>>(Wq,  CC,     CC,  bq_op);
    conv_w<<<dim3(32, 32), wblk>>>(Wkv, 2 * CC, CC,  bk_op);
    conv_w<<<dim3(32, 32), wblk>>>(Wout, CC,    CC,  bo_op);
    conv_w<<<dim3(8, 32),  wblk>>>(Woff, NHEADS * NPTS * 2, NHEADS * NPTS * 2, bf_op);

    const int cablk = (int)(((size_t)MM * 128 + 255) / 256);

    // q = query @ Wq + bq ; off = query @ Woff + boff
    conv_act<<<cablk, 256>>>(query, abig);
    gemm_hmma<<<dim3(4, mtiles), 512, SMEM_SZ>>>(abig, bq_op, bq, qb, MM, CC, CC);
    gemm_hmma<<<dim3(1, mtiles), 512, SMEM_SZ>>>(abig, bf_op, boff, offp, MM, 128, 128);

    // k = ref @ Wkv[:, :C] + bkv[:C]
    conv_act<<<cablk, 256>>>(ref, abig);
    gemm_hmma<<<dim3(4, mtiles), 512, SMEM_SZ>>>(abig, bk_op, bkv, kb, MM, CC, CC);

    // sampling + attention; writes bf16 split operand directly into abig
    {
        int warps = MM * NHEADS;
        int blocks = (warps * 32 + 255) / 256;
        sample_attn_kernel<<<blocks, 256>>>(qb, kb, offp, abig);
    }

    // out = attn @ Wout + bout
    gemm_hmma<<<dim3(4, mtiles), 512, SMEM_SZ>>>(abig, bo_op, bout, outp, MM, CC, CC);
}

// round 5
// speedup vs baseline: 1.2831x; 1.2831x over previous
#include <cuda_runtime.h>
#include <cuda_bf16.h>
#include <math.h>
#include <cstdint>

// Problem constants
#define BB 8
#define HH 37
#define WW 37
#define NN (HH * WW)          // 1369
#define CC 1024
#define MM (BB * NN)          // 10952
#define NHEADS 8
#define HD 128
#define NPTS 8
#define K3 3072               // split-K: A=[Ah|Al|Ah], B=[Bh|Bh|Bl]
#define NCHUNK (K3 / 64)      // 48
#define STAGES 3
#define STAGE_BYTES 32768     // A 16K + B 16K
#define SMEM_SZ (STAGES * STAGE_BYTES)

// ---------------------------------------------------------------------------
// Scratch
// ---------------------------------------------------------------------------
__device__ __nv_bfloat16 g_abig[MM * K3];
__device__ __nv_bfloat16 g_bop_q[CC * K3];
__device__ __nv_bfloat16 g_bop_k[CC * K3];
__device__ __nv_bfloat16 g_bop_o[CC * K3];
__device__ __nv_bfloat16 g_bop_f[128 * K3];
__device__ float g_q[MM * CC];
__device__ float g_k[MM * CC];
__device__ float g_offp[MM * 128];

// ---------------------------------------------------------------------------
__device__ __forceinline__ uint32_t smem_u32(const void* p) {
    uint32_t a;
    asm("{ .reg .u64 t; cvta.to.shared.u64 t, %1; cvt.u32.u64 %0, t; }" : "=r"(a) : "l"(p));
    return a;
}
__device__ __forceinline__ void cp16(uint32_t dst, const void* src, bool valid) {
    int sz = valid ? 16 : 0;
    asm volatile("cp.async.cg.shared.global [%0], [%1], 16, %2;"
                 :: "r"(dst), "l"(src), "r"(sz) : "memory");
}
#define CP_COMMIT() asm volatile("cp.async.commit_group;" ::: "memory")
#define CP_WAIT1()  asm volatile("cp.async.wait_group 1;" ::: "memory")

__device__ __forceinline__ void ldsm4(uint32_t* r, uint32_t addr) {
    asm volatile("ldmatrix.sync.aligned.m8n8.x4.shared.b16 {%0,%1,%2,%3}, [%4];"
                 : "=r"(r[0]), "=r"(r[1]), "=r"(r[2]), "=r"(r[3]) : "r"(addr));
}
__device__ __forceinline__ void mma16816(float* c, const uint32_t* a, const uint32_t* b) {
    asm volatile(
        "mma.sync.aligned.m16n8k16.row.col.f32.bf16.bf16.f32 "
        "{%0,%1,%2,%3},{%4,%5,%6,%7},{%8,%9},{%0,%1,%2,%3};"
        : "+f"(c[0]), "+f"(c[1]), "+f"(c[2]), "+f"(c[3])
        : "r"(a[0]), "r"(a[1]), "r"(a[2]), "r"(a[3]), "r"(b[0]), "r"(b[1]));
}

// ---------------------------------------------------------------------------
// bf16 HMMA GEMM: C[M x 128-tile] = A[M,3072] x Bop[n][3072]^T + bias
// CTA 128x128, 8 warps (2 m x 4 n), warp tile 64x32. 3-stage cp.async pipeline.
// (R3 config: 96KB smem -> 2 CTAs/SM, 688-CTA grid.)
// ---------------------------------------------------------------------------
__global__ __launch_bounds__(256)
void gemm_hmma(const __nv_bfloat16* __restrict__ A, const __nv_bfloat16* __restrict__ B,
               const float* __restrict__ bias, float* __restrict__ C, int M, int ldc) {
    extern __shared__ char smem[];
    const uint32_t sb0 = smem_u32(smem);
    const int tid = threadIdx.x, wid = tid >> 5, lane = tid & 31;
    const int m0 = blockIdx.y * 128;
    const int col0 = blockIdx.x * 128;
    const __nv_bfloat16* Bc0 = B + (size_t)col0 * K3;

    auto load_stage = [&](int ck, int stage) {
        const uint32_t sa = sb0 + stage * STAGE_BYTES;
        const __nv_bfloat16* Ac = A + ck * 64;
        const __nv_bfloat16* Bc = Bc0 + ck * 64;
#pragma unroll
        for (int i = 0; i < 4; i++) {
            int id = tid + i * 256;
            int row = id >> 3, c16 = id & 7;
            int gr = m0 + row;
            bool v = gr < M;
            int grc = v ? gr : (M - 1);
            uint32_t dst = sa + row * 128 + (((uint32_t)c16 ^ (row & 7)) << 4);
            cp16(dst, Ac + (size_t)grc * K3 + c16 * 8, v);
        }
#pragma unroll
        for (int i = 0; i < 4; i++) {
            int id = tid + i * 256;
            int row = id >> 3, c16 = id & 7;
            uint32_t dst = sa + 16384 + row * 128 + (((uint32_t)c16 ^ (row & 7)) << 4);
            cp16(dst, Bc + (size_t)row * K3 + c16 * 8, true);
        }
        CP_COMMIT();
    };

    float acc[4][4][4];
#pragma unroll
    for (int mt = 0; mt < 4; mt++)
#pragma unroll
        for (int nt = 0; nt < 4; nt++)
#pragma unroll
            for (int j = 0; j < 4; j++) acc[mt][nt][j] = 0.0f;

    load_stage(0, 0);
    load_stage(1, 1);

    const int wm = (wid & 1) * 64;
    const int wn = (wid >> 1) * 32;

    for (int c = 0; c < NCHUNK; c++) {
        CP_WAIT1();
        __syncthreads();
        if (c + 2 < NCHUNK) load_stage(c + 2, (c + 2) % STAGES);
        else CP_COMMIT();

        const uint32_t sa = sb0 + (c % STAGES) * STAGE_BYTES;
        const uint32_t sbB = sa + 16384;

#pragma unroll
        for (int ks = 0; ks < 4; ks++) {
            uint32_t af[4][4];
#pragma unroll
            for (int mt = 0; mt < 4; mt++) {
                int row = wm + mt * 16 + (lane & 15);
                uint32_t c16 = (uint32_t)(ks * 2 + (lane >> 4)) ^ (row & 7);
                ldsm4(af[mt], sa + row * 128 + (c16 << 4));
            }
            uint32_t bf[4][2];
#pragma unroll
            for (int nt2 = 0; nt2 < 2; nt2++) {
                int group = lane >> 3;
                int nrow = wn + nt2 * 16 + (group >> 1) * 8 + (lane & 7);
                uint32_t c16 = (uint32_t)(ks * 2 + (group & 1)) ^ (nrow & 7);
                uint32_t r[4];
                ldsm4(r, sbB + nrow * 128 + (c16 << 4));
                bf[nt2 * 2][0] = r[0]; bf[nt2 * 2][1] = r[1];
                bf[nt2 * 2 + 1][0] = r[2]; bf[nt2 * 2 + 1][1] = r[3];
            }
#pragma unroll
            for (int mt = 0; mt < 4; mt++)
#pragma unroll
                for (int nt = 0; nt < 4; nt++)
                    mma16816(acc[mt][nt], af[mt], bf[nt]);
        }
        __syncthreads();
    }

    const int lr = lane >> 2, lc = (lane & 3) * 2;
#pragma unroll
    for (int mt = 0; mt < 4; mt++) {
#pragma unroll
        for (int nt = 0; nt < 4; nt++) {
            int r0 = m0 + wm + mt * 16 + lr;
            int cb = col0 + wn + nt * 8 + lc;
            float b0 = bias[cb], b1 = bias[cb + 1];
            if (r0 < M) {
                float2 v = make_float2(acc[mt][nt][0] + b0, acc[mt][nt][1] + b1);
                *reinterpret_cast<float2*>(C + (size_t)r0 * ldc + cb) = v;
            }
            int r1 = r0 + 8;
            if (r1 < M) {
                float2 v = make_float2(acc[mt][nt][2] + b0, acc[mt][nt][3] + b1);
                *reinterpret_cast<float2*>(C + (size_t)r1 * ldc + cb) = v;
            }
        }
    }
}

// ---------------------------------------------------------------------------
// Activation conversion: fp32 [M][1024] -> bf16 [M][3072] as [hi | lo | hi]
// ---------------------------------------------------------------------------
__global__ __launch_bounds__(256)
void conv_act(const float* __restrict__ A, __nv_bfloat16* __restrict__ out) {
    size_t i = (size_t)blockIdx.x * blockDim.x + threadIdx.x;
    if (i >= (size_t)MM * 128) return;
    size_t r = i >> 7;
    int c8 = (int)(i & 127) * 8;
    const float4* p = reinterpret_cast<const float4*>(A + r * CC + c8);
    float4 v0 = p[0], v1 = p[1];
    float vv[8] = {v0.x, v0.y, v0.z, v0.w, v1.x, v1.y, v1.z, v1.w};
    __nv_bfloat16 hi[8], lo[8];
#pragma unroll
    for (int j = 0; j < 8; j++) {
        hi[j] = __float2bfloat16(vv[j]);
        lo[j] = __float2bfloat16(vv[j] - __bfloat162float(hi[j]));
    }
    __nv_bfloat16* rp = out + r * K3;
    *reinterpret_cast<uint4*>(rp + c8)        = *reinterpret_cast<uint4*>(hi);
    *reinterpret_cast<uint4*>(rp + c8 + 1024) = *reinterpret_cast<uint4*>(lo);
    *reinterpret_cast<uint4*>(rp + c8 + 2048) = *reinterpret_cast<uint4*>(hi);
}

// ---------------------------------------------------------------------------
// Weight conversion (transpose): W[1024][ldw] cols [0,nvalid) ->
// Bop[n][3072] = [hi | hi | lo]
// ---------------------------------------------------------------------------
__global__ __launch_bounds__(256)
void conv_w(const float* __restrict__ W, int ldw, int nvalid, __nv_bfloat16* __restrict__ Bop) {
    __shared__ float t[32][33];
    const int n0 = blockIdx.x * 32, k0 = blockIdx.y * 32;
    const int tx = threadIdx.x, ty = threadIdx.y;
#pragma unroll
    for (int j = ty; j < 32; j += 8) {
        int n = n0 + tx, k = k0 + j;
        t[j][tx] = (n < nvalid) ? W[(size_t)k * ldw + n] : 0.0f;
    }
    __syncthreads();
#pragma unroll
    for (int j = ty; j < 32; j += 8) {
        int n = n0 + j, k = k0 + tx;
        float v = t[tx][j];
        __nv_bfloat16 h = __float2bfloat16(v);
        __nv_bfloat16 l = __float2bfloat16(v - __bfloat162float(h));
        __nv_bfloat16* row = Bop + (size_t)n * K3;
        row[k] = h; row[k + 1024] = h; row[k + 2048] = l;
    }
}

// ---------------------------------------------------------------------------
// Sampling + attention. One warp per (b, n, head). off stride = 128.
// Writes the bf16 split operand [hi|lo|hi] directly (feeds the final GEMM).
// ---------------------------------------------------------------------------
__global__ __launch_bounds__(256)
void sample_attn_kernel(const float* __restrict__ q, const float* __restrict__ k,
                        const float* __restrict__ off, __nv_bfloat16* __restrict__ outop) {
    const int gwarp = (blockIdx.x * blockDim.x + threadIdx.x) >> 5;
    const int lane = threadIdx.x & 31;
    if (gwarp >= MM * NHEADS) return;

    const int h = gwarp & (NHEADS - 1);
    const int m = gwarp >> 3;
    const int n = m % NN;
    const int b = m / NN;

    const int ch = h * HD + lane * 4;
    float4 qv = *reinterpret_cast<const float4*>(q + (size_t)m * CC + ch);

    const int iy_n = n / WW;
    const int ix_n = n % WW;
    const float cy = -1.0f + 2.0f * (float)iy_n / (float)(HH - 1);
    const float cx = -1.0f + 2.0f * (float)ix_n / (float)(WW - 1);

    const float* offp = off + (size_t)m * 128 + h * (NPTS * 2);
    const float* kb = k + (size_t)b * NN * CC;

    float sk[NPTS][4];
    float score[NPTS];
    const float scale = 0.08838834764831845f;

#pragma unroll
    for (int p = 0; p < NPTS; p++) {
        float l0 = cy + offp[2 * p + 0];
        float l1 = cx + offp[2 * p + 1];
        float ix = (l0 + 1.0f) * 0.5f * (float)(WW - 1);
        float iy = (l1 + 1.0f) * 0.5f * (float)(HH - 1);
        ix = fminf(fmaxf(ix, 0.0f), (float)(WW - 1));
        iy = fminf(fmaxf(iy, 0.0f), (float)(HH - 1));
        float x0f = floorf(ix), y0f = floorf(iy);
        float wx = ix - x0f, wy = iy - y0f;
        int x0 = (int)x0f, y0 = (int)y0f;
        int x1 = min(x0 + 1, WW - 1);
        int y1 = min(y0 + 1, HH - 1);

        const float4 g00 = *reinterpret_cast<const float4*>(kb + (size_t)(y0 * WW + x0) * CC + ch);
        const float4 g01 = *reinterpret_cast<const float4*>(kb + (size_t)(y0 * WW + x1) * CC + ch);
        const float4 g10 = *reinterpret_cast<const float4*>(kb + (size_t)(y1 * WW + x0) * CC + ch);
        const float4 g11 = *reinterpret_cast<const float4*>(kb + (size_t)(y1 * WW + x1) * CC + ch);

        float w00 = (1.0f - wy) * (1.0f - wx);
        float w01 = (1.0f - wy) * wx;
        float w10 = wy * (1.0f - wx);
        float w11 = wy * wx;

        sk[p][0] = g00.x * w00 + g01.x * w01 + g10.x * w10 + g11.x * w11;
        sk[p][1] = g00.y * w00 + g01.y * w01 + g10.y * w10 + g11.y * w11;
        sk[p][2] = g00.z * w00 + g01.z * w01 + g10.z * w10 + g11.z * w11;
        sk[p][3] = g00.w * w00 + g01.w * w01 + g10.w * w10 + g11.w * w11;

        float s = qv.x * sk[p][0] + qv.y * sk[p][1] + qv.z * sk[p][2] + qv.w * sk[p][3];
#pragma unroll
        for (int d = 16; d > 0; d >>= 1)
            s += __shfl_xor_sync(0xFFFFFFFFu, s, d);
        score[p] = s * scale;
    }

    float mx = score[0];
#pragma unroll
    for (int p = 1; p < NPTS; p++) mx = fmaxf(mx, score[p]);
    float denom = 0.0f;
    float e[NPTS];
#pragma unroll
    for (int p = 0; p < NPTS; p++) { e[p] = expf(score[p] - mx); denom += e[p]; }
    float inv = 1.0f / denom;

    float av[4] = {0.f, 0.f, 0.f, 0.f};
#pragma unroll
    for (int p = 0; p < NPTS; p++) {
        float a = e[p] * inv;
        av[0] += a * sk[p][0];
        av[1] += a * sk[p][1];
        av[2] += a * sk[p][2];
        av[3] += a * sk[p][3];
    }

    // write bf16 split operand directly: [hi | lo | hi]
    __nv_bfloat16 hi[4], lo[4];
#pragma unroll
    for (int j = 0; j < 4; j++) {
        hi[j] = __float2bfloat16(av[j]);
        lo[j] = __float2bfloat16(av[j] - __bfloat162float(hi[j]));
    }
    __nv_bfloat16* rp = outop + (size_t)m * K3;
    *reinterpret_cast<uint2*>(rp + ch)        = *reinterpret_cast<uint2*>(hi);
    *reinterpret_cast<uint2*>(rp + ch + 1024) = *reinterpret_cast<uint2*>(lo);
    *reinterpret_cast<uint2*>(rp + ch + 2048) = *reinterpret_cast<uint2*>(hi);
}

// ---------------------------------------------------------------------------
extern "C" void kernel_launch(void* const* d_in, const int* in_sizes, int n_in,
                              void* d_out, int out_size) {
    const float* query = (const float*)d_in[0];
    const float* ref   = (const float*)d_in[1];
    const float* Wq    = (const float*)d_in[2];
    const float* bq    = (const float*)d_in[3];
    const float* Wkv   = (const float*)d_in[4];
    const float* bkv   = (const float*)d_in[5];
    const float* Woff  = (const float*)d_in[6];
    const float* boff  = (const float*)d_in[7];
    const float* Wout  = (const float*)d_in[8];
    const float* bout  = (const float*)d_in[9];
    float* outp = (float*)d_out;

    __nv_bfloat16 *abig, *bq_op, *bk_op, *bo_op, *bf_op;
    float *qb, *kb, *offp;
    cudaGetSymbolAddress((void**)&abig,  g_abig);
    cudaGetSymbolAddress((void**)&bq_op, g_bop_q);
    cudaGetSymbolAddress((void**)&bk_op, g_bop_k);
    cudaGetSymbolAddress((void**)&bo_op, g_bop_o);
    cudaGetSymbolAddress((void**)&bf_op, g_bop_f);
    cudaGetSymbolAddress((void**)&qb,    g_q);
    cudaGetSymbolAddress((void**)&kb,    g_k);
    cudaGetSymbolAddress((void**)&offp,  g_offp);

    cudaFuncSetAttribute(gemm_hmma, cudaFuncAttributeMaxDynamicSharedMemorySize, SMEM_SZ);

    const int mtiles = (MM + 127) / 128;  // 86
    dim3 wblk(32, 8);

    // weight conversions
    conv_w<<<dim3(32, 32), wblk>>>(Wq,  CC,     CC,  bq_op);
    conv_w<<<dim3(32, 32), wblk>>>(Wkv, 2 * CC, CC,  bk_op);
    conv_w<<<dim3(32, 32), wblk>>>(Wout, CC,    CC,  bo_op);
    conv_w<<<dim3(4, 32),  wblk>>>(Woff, NHEADS * NPTS * 2, NHEADS * NPTS * 2, bf_op);

    const int cablk = (int)(((size_t)MM * 128 + 255) / 256);

    // q = query @ Wq + bq ; off = query @ Woff + boff
    conv_act<<<cablk, 256>>>(query, abig);
    gemm_hmma<<<dim3(8, mtiles), 256, SMEM_SZ>>>(abig, bq_op, bq, qb, MM, CC);
    gemm_hmma<<<dim3(1, mtiles), 256, SMEM_SZ>>>(abig, bf_op, boff, offp, MM, 128);

    // k = ref @ Wkv[:, :C] + bkv[:C]
    conv_act<<<cablk, 256>>>(ref, abig);
    gemm_hmma<<<dim3(8, mtiles), 256, SMEM_SZ>>>(abig, bk_op, bkv, kb, MM, CC);

    // sampling + attention; writes bf16 split operand directly into abig
    {
        int warps = MM * NHEADS;
        int blocks = (warps * 32 + 255) / 256;
        sample_attn_kernel<<<blocks, 256>>>(qb, kb, offp, abig);
    }

    // out = attn @ Wout + bout
    gemm_hmma<<<dim3(8, mtiles), 256, SMEM_SZ>>>(abig, bo_op, bout, outp, MM, CC);
}

// round 6
// speedup vs baseline: 1.3974x; 1.0891x over previous
#include <cuda_runtime.h>
#include <cuda_bf16.h>
#include <math.h>
#include <cstdint>

// Problem constants
#define BB 8
#define HH 37
#define WW 37
#define NN (HH * WW)          // 1369
#define CC 1024
#define MM (BB * NN)          // 10952
#define NHEADS 8
#define HD 128
#define NPTS 8
#define K3 3072               // split-K: A=[Ah|Al|Ah], B=[Bh|Bh|Bl]
#define NCHUNK (K3 / 64)      // 48
#define STAGES 3
#define STAGE_BYTES 32768     // A 16K + B 16K
#define SMEM_SZ (STAGES * STAGE_BYTES)
#define MTILES 86             // ceil(MM/128)

// ---------------------------------------------------------------------------
// Scratch
// ---------------------------------------------------------------------------
__device__ __nv_bfloat16 g_abig[MM * K3];     // query split; later attn split
__device__ __nv_bfloat16 g_abig2[MM * K3];    // ref split
__device__ __nv_bfloat16 g_bop_q[CC * K3];
__device__ __nv_bfloat16 g_bop_k[CC * K3];
__device__ __nv_bfloat16 g_bop_o[CC * K3];
__device__ __nv_bfloat16 g_bop_f[128 * K3];
__device__ float g_q[MM * CC];
__device__ float g_k[MM * CC];
__device__ float g_offp[MM * 128];

// ---------------------------------------------------------------------------
__device__ __forceinline__ uint32_t smem_u32(const void* p) {
    uint32_t a;
    asm("{ .reg .u64 t; cvta.to.shared.u64 t, %1; cvt.u32.u64 %0, t; }" : "=r"(a) : "l"(p));
    return a;
}
__device__ __forceinline__ void cp16(uint32_t dst, const void* src, bool valid) {
    int sz = valid ? 16 : 0;
    asm volatile("cp.async.cg.shared.global [%0], [%1], 16, %2;"
                 :: "r"(dst), "l"(src), "r"(sz) : "memory");
}
#define CP_COMMIT() asm volatile("cp.async.commit_group;" ::: "memory")
#define CP_WAIT1()  asm volatile("cp.async.wait_group 1;" ::: "memory")

__device__ __forceinline__ void ldsm4(uint32_t* r, uint32_t addr) {
    asm volatile("ldmatrix.sync.aligned.m8n8.x4.shared.b16 {%0,%1,%2,%3}, [%4];"
                 : "=r"(r[0]), "=r"(r[1]), "=r"(r[2]), "=r"(r[3]) : "r"(addr));
}
__device__ __forceinline__ void mma16816(float* c, const uint32_t* a, const uint32_t* b) {
    asm volatile(
        "mma.sync.aligned.m16n8k16.row.col.f32.bf16.bf16.f32 "
        "{%0,%1,%2,%3},{%4,%5,%6,%7},{%8,%9},{%0,%1,%2,%3};"
        : "+f"(c[0]), "+f"(c[1]), "+f"(c[2]), "+f"(c[3])
        : "r"(a[0]), "r"(a[1]), "r"(a[2]), "r"(a[3]), "r"(b[0]), "r"(b[1]));
}

// ---------------------------------------------------------------------------
// GEMM body (R3-proven config): CTA 128x128, 8 warps 64x32, 3-stage cp.async
// ---------------------------------------------------------------------------
__device__ __forceinline__
void gemm_body(const __nv_bfloat16* __restrict__ A, const __nv_bfloat16* __restrict__ B,
               const float* __restrict__ bias, float* __restrict__ C,
               int ldc, int m0, int col0, char* smem) {
    const uint32_t sb0 = smem_u32(smem);
    const int tid = threadIdx.x, wid = tid >> 5, lane = tid & 31;
    const __nv_bfloat16* Bc0 = B + (size_t)col0 * K3;

    auto load_stage = [&](int ck, int stage) {
        const uint32_t sa = sb0 + stage * STAGE_BYTES;
        const __nv_bfloat16* Ac = A + ck * 64;
        const __nv_bfloat16* Bc = Bc0 + ck * 64;
#pragma unroll
        for (int i = 0; i < 4; i++) {
            int id = tid + i * 256;
            int row = id >> 3, c16 = id & 7;
            int gr = m0 + row;
            bool v = gr < MM;
            int grc = v ? gr : (MM - 1);
            uint32_t dst = sa + row * 128 + (((uint32_t)c16 ^ (row & 7)) << 4);
            cp16(dst, Ac + (size_t)grc * K3 + c16 * 8, v);
        }
#pragma unroll
        for (int i = 0; i < 4; i++) {
            int id = tid + i * 256;
            int row = id >> 3, c16 = id & 7;
            uint32_t dst = sa + 16384 + row * 128 + (((uint32_t)c16 ^ (row & 7)) << 4);
            cp16(dst, Bc + (size_t)row * K3 + c16 * 8, true);
        }
        CP_COMMIT();
    };

    float acc[4][4][4];
#pragma unroll
    for (int mt = 0; mt < 4; mt++)
#pragma unroll
        for (int nt = 0; nt < 4; nt++)
#pragma unroll
            for (int j = 0; j < 4; j++) acc[mt][nt][j] = 0.0f;

    load_stage(0, 0);
    load_stage(1, 1);

    const int wm = (wid & 1) * 64;
    const int wn = (wid >> 1) * 32;

    for (int c = 0; c < NCHUNK; c++) {
        CP_WAIT1();
        __syncthreads();
        if (c + 2 < NCHUNK) load_stage(c + 2, (c + 2) % STAGES);
        else CP_COMMIT();

        const uint32_t sa = sb0 + (c % STAGES) * STAGE_BYTES;
        const uint32_t sbB = sa + 16384;

#pragma unroll
        for (int ks = 0; ks < 4; ks++) {
            uint32_t af[4][4];
#pragma unroll
            for (int mt = 0; mt < 4; mt++) {
                int row = wm + mt * 16 + (lane & 15);
                uint32_t c16 = (uint32_t)(ks * 2 + (lane >> 4)) ^ (row & 7);
                ldsm4(af[mt], sa + row * 128 + (c16 << 4));
            }
            uint32_t bf[4][2];
#pragma unroll
            for (int nt2 = 0; nt2 < 2; nt2++) {
                int group = lane >> 3;
                int nrow = wn + nt2 * 16 + (group >> 1) * 8 + (lane & 7);
                uint32_t c16 = (uint32_t)(ks * 2 + (group & 1)) ^ (nrow & 7);
                uint32_t r[4];
                ldsm4(r, sbB + nrow * 128 + (c16 << 4));
                bf[nt2 * 2][0] = r[0]; bf[nt2 * 2][1] = r[1];
                bf[nt2 * 2 + 1][0] = r[2]; bf[nt2 * 2 + 1][1] = r[3];
            }
#pragma unroll
            for (int mt = 0; mt < 4; mt++)
#pragma unroll
                for (int nt = 0; nt < 4; nt++)
                    mma16816(acc[mt][nt], af[mt], bf[nt]);
        }
        __syncthreads();
    }

    const int lr = lane >> 2, lc = (lane & 3) * 2;
#pragma unroll
    for (int mt = 0; mt < 4; mt++) {
#pragma unroll
        for (int nt = 0; nt < 4; nt++) {
            int r0 = m0 + wm + mt * 16 + lr;
            int cb = col0 + wn + nt * 8 + lc;
            float b0 = bias[cb], b1 = bias[cb + 1];
            if (r0 < MM) {
                float2 v = make_float2(acc[mt][nt][0] + b0, acc[mt][nt][1] + b1);
                *reinterpret_cast<float2*>(C + (size_t)r0 * ldc + cb) = v;
            }
            int r1 = r0 + 8;
            if (r1 < MM) {
                float2 v = make_float2(acc[mt][nt][2] + b0, acc[mt][nt][3] + b1);
                *reinterpret_cast<float2*>(C + (size_t)r1 * ldc + cb) = v;
            }
        }
    }
}

// Merged q + k + off GEMM launch. Flattened grid of 17*MTILES CTAs.
// t = bx / MTILES: [0,8) q cols, [8,16) k cols, 16 = off.
__global__ __launch_bounds__(256)
void gemm3(const __nv_bfloat16* __restrict__ Aq, const __nv_bfloat16* __restrict__ Ak,
           const __nv_bfloat16* __restrict__ Bq, const __nv_bfloat16* __restrict__ Bk,
           const __nv_bfloat16* __restrict__ Bf,
           const float* __restrict__ bq, const float* __restrict__ bkv,
           const float* __restrict__ boff,
           float* __restrict__ Cq, float* __restrict__ Ck, float* __restrict__ Coff) {
    extern __shared__ char smem[];
    const int bx = blockIdx.x;
    const int t = bx / MTILES;
    const int m0 = (bx % MTILES) * 128;
    if (t < 8) {
        gemm_body(Aq, Bq, bq, Cq, CC, m0, t * 128, smem);
    } else if (t < 16) {
        gemm_body(Ak, Bk, bkv, Ck, CC, m0, (t - 8) * 128, smem);
    } else {
        gemm_body(Aq, Bf, boff, Coff, 128, m0, 0, smem);
    }
}

// Final GEMM: out = attn_split @ Wout + bout
__global__ __launch_bounds__(256)
void gemm_hmma(const __nv_bfloat16* __restrict__ A, const __nv_bfloat16* __restrict__ B,
               const float* __restrict__ bias, float* __restrict__ C) {
    extern __shared__ char smem[];
    gemm_body(A, B, bias, C, CC, blockIdx.y * 128, blockIdx.x * 128, smem);
}

// ---------------------------------------------------------------------------
// Merged activation conversion: fp32 [M][1024] -> bf16 [M][3072] [hi|lo|hi]
// blockIdx.y: 0 = query->abig, 1 = ref->abig2
// ---------------------------------------------------------------------------
__global__ __launch_bounds__(256)
void conv_act2(const float* __restrict__ A0, const float* __restrict__ A1,
               __nv_bfloat16* __restrict__ O0, __nv_bfloat16* __restrict__ O1) {
    const float* A = blockIdx.y ? A1 : A0;
    __nv_bfloat16* out = blockIdx.y ? O1 : O0;
    size_t i = (size_t)blockIdx.x * blockDim.x + threadIdx.x;
    if (i >= (size_t)MM * 128) return;
    size_t r = i >> 7;
    int c8 = (int)(i & 127) * 8;
    const float4* p = reinterpret_cast<const float4*>(A + r * CC + c8);
    float4 v0 = p[0], v1 = p[1];
    float vv[8] = {v0.x, v0.y, v0.z, v0.w, v1.x, v1.y, v1.z, v1.w};
    __nv_bfloat16 hi[8], lo[8];
#pragma unroll
    for (int j = 0; j < 8; j++) {
        hi[j] = __float2bfloat16(vv[j]);
        lo[j] = __float2bfloat16(vv[j] - __bfloat162float(hi[j]));
    }
    __nv_bfloat16* rp = out + r * K3;
    *reinterpret_cast<uint4*>(rp + c8)        = *reinterpret_cast<uint4*>(hi);
    *reinterpret_cast<uint4*>(rp + c8 + 1024) = *reinterpret_cast<uint4*>(lo);
    *reinterpret_cast<uint4*>(rp + c8 + 2048) = *reinterpret_cast<uint4*>(hi);
}

// ---------------------------------------------------------------------------
// Merged weight conversion: blockIdx.z selects {Wq, Wkv, Wout, Woff}
// Bop[n][3072] = [hi | hi | lo]
// ---------------------------------------------------------------------------
__global__ __launch_bounds__(256)
void conv_w4(const float* __restrict__ W0, const float* __restrict__ W1,
             const float* __restrict__ W2, const float* __restrict__ W3,
             __nv_bfloat16* __restrict__ O0, __nv_bfloat16* __restrict__ O1,
             __nv_bfloat16* __restrict__ O2, __nv_bfloat16* __restrict__ O3) {
    const int z = blockIdx.z;
    const float* W;
    __nv_bfloat16* Bop;
    int ldw, nvalid;
    if (z == 0)      { W = W0; Bop = O0; ldw = CC;     nvalid = CC; }
    else if (z == 1) { W = W1; Bop = O1; ldw = 2 * CC; nvalid = CC; }
    else if (z == 2) { W = W2; Bop = O2; ldw = CC;     nvalid = CC; }
    else             { W = W3; Bop = O3; ldw = 128;    nvalid = 128;
                       if (blockIdx.x >= 4) return; }

    __shared__ float t[32][33];
    const int n0 = blockIdx.x * 32, k0 = blockIdx.y * 32;
    const int tx = threadIdx.x, ty = threadIdx.y;
#pragma unroll
    for (int j = ty; j < 32; j += 8) {
        int n = n0 + tx, k = k0 + j;
        t[j][tx] = (n < nvalid) ? W[(size_t)k * ldw + n] : 0.0f;
    }
    __syncthreads();
#pragma unroll
    for (int j = ty; j < 32; j += 8) {
        int n = n0 + j, k = k0 + tx;
        float v = t[tx][j];
        __nv_bfloat16 h = __float2bfloat16(v);
        __nv_bfloat16 l = __float2bfloat16(v - __bfloat162float(h));
        __nv_bfloat16* row = Bop + (size_t)n * K3;
        row[k] = h; row[k + 1024] = h; row[k + 2048] = l;
    }
}

// ---------------------------------------------------------------------------
// Sampling + attention. One warp per (b, n, head). off stride = 128.
// Writes the bf16 split operand [hi|lo|hi] directly.
// ---------------------------------------------------------------------------
__global__ __launch_bounds__(256)
void sample_attn_kernel(const float* __restrict__ q, const float* __restrict__ k,
                        const float* __restrict__ off, __nv_bfloat16* __restrict__ outop) {
    const int gwarp = (blockIdx.x * blockDim.x + threadIdx.x) >> 5;
    const int lane = threadIdx.x & 31;
    if (gwarp >= MM * NHEADS) return;

    const int h = gwarp & (NHEADS - 1);
    const int m = gwarp >> 3;
    const int n = m % NN;
    const int b = m / NN;

    const int ch = h * HD + lane * 4;
    float4 qv = *reinterpret_cast<const float4*>(q + (size_t)m * CC + ch);

    const int iy_n = n / WW;
    const int ix_n = n % WW;
    const float cy = -1.0f + 2.0f * (float)iy_n / (float)(HH - 1);
    const float cx = -1.0f + 2.0f * (float)ix_n / (float)(WW - 1);

    const float* offp = off + (size_t)m * 128 + h * (NPTS * 2);
    const float* kb = k + (size_t)b * NN * CC;

    float sk[NPTS][4];
    float score[NPTS];
    const float scale = 0.08838834764831845f;

#pragma unroll
    for (int p = 0; p < NPTS; p++) {
        float l0 = cy + offp[2 * p + 0];
        float l1 = cx + offp[2 * p + 1];
        float ix = (l0 + 1.0f) * 0.5f * (float)(WW - 1);
        float iy = (l1 + 1.0f) * 0.5f * (float)(HH - 1);
        ix = fminf(fmaxf(ix, 0.0f), (float)(WW - 1));
        iy = fminf(fmaxf(iy, 0.0f), (float)(HH - 1));
        float x0f = floorf(ix), y0f = floorf(iy);
        float wx = ix - x0f, wy = iy - y0f;
        int x0 = (int)x0f, y0 = (int)y0f;
        int x1 = min(x0 + 1, WW - 1);
        int y1 = min(y0 + 1, HH - 1);

        const float4 g00 = *reinterpret_cast<const float4*>(kb + (size_t)(y0 * WW + x0) * CC + ch);
        const float4 g01 = *reinterpret_cast<const float4*>(kb + (size_t)(y0 * WW + x1) * CC + ch);
        const float4 g10 = *reinterpret_cast<const float4*>(kb + (size_t)(y1 * WW + x0) * CC + ch);
        const float4 g11 = *reinterpret_cast<const float4*>(kb + (size_t)(y1 * WW + x1) * CC + ch);

        float w00 = (1.0f - wy) * (1.0f - wx);
        float w01 = (1.0f - wy) * wx;
        float w10 = wy * (1.0f - wx);
        float w11 = wy * wx;

        sk[p][0] = g00.x * w00 + g01.x * w01 + g10.x * w10 + g11.x * w11;
        sk[p][1] = g00.y * w00 + g01.y * w01 + g10.y * w10 + g11.y * w11;
        sk[p][2] = g00.z * w00 + g01.z * w01 + g10.z * w10 + g11.z * w11;
        sk[p][3] = g00.w * w00 + g01.w * w01 + g10.w * w10 + g11.w * w11;

        float s = qv.x * sk[p][0] + qv.y * sk[p][1] + qv.z * sk[p][2] + qv.w * sk[p][3];
#pragma unroll
        for (int d = 16; d > 0; d >>= 1)
            s += __shfl_xor_sync(0xFFFFFFFFu, s, d);
        score[p] = s * scale;
    }

    float mx = score[0];
#pragma unroll
    for (int p = 1; p < NPTS; p++) mx = fmaxf(mx, score[p]);
    float denom = 0.0f;
    float e[NPTS];
#pragma unroll
    for (int p = 0; p < NPTS; p++) { e[p] = expf(score[p] - mx); denom += e[p]; }
    float inv = 1.0f / denom;

    float av[4] = {0.f, 0.f, 0.f, 0.f};
#pragma unroll
    for (int p = 0; p < NPTS; p++) {
        float a = e[p] * inv;
        av[0] += a * sk[p][0];
        av[1] += a * sk[p][1];
        av[2] += a * sk[p][2];
        av[3] += a * sk[p][3];
    }

    __nv_bfloat16 hi[4], lo[4];
#pragma unroll
    for (int j = 0; j < 4; j++) {
        hi[j] = __float2bfloat16(av[j]);
        lo[j] = __float2bfloat16(av[j] - __bfloat162float(hi[j]));
    }
    __nv_bfloat16* rp = outop + (size_t)m * K3;
    *reinterpret_cast<uint2*>(rp + ch)        = *reinterpret_cast<uint2*>(hi);
    *reinterpret_cast<uint2*>(rp + ch + 1024) = *reinterpret_cast<uint2*>(lo);
    *reinterpret_cast<uint2*>(rp + ch + 2048) = *reinterpret_cast<uint2*>(hi);
}

// ---------------------------------------------------------------------------
extern "C" void kernel_launch(void* const* d_in, const int* in_sizes, int n_in,
                              void* d_out, int out_size) {
    const float* query = (const float*)d_in[0];
    const float* ref   = (const float*)d_in[1];
    const float* Wq    = (const float*)d_in[2];
    const float* bq    = (const float*)d_in[3];
    const float* Wkv   = (const float*)d_in[4];
    const float* bkv   = (const float*)d_in[5];
    const float* Woff  = (const float*)d_in[6];
    const float* boff  = (const float*)d_in[7];
    const float* Wout  = (const float*)d_in[8];
    const float* bout  = (const float*)d_in[9];
    float* outp = (float*)d_out;

    __nv_bfloat16 *abig, *abig2, *bq_op, *bk_op, *bo_op, *bf_op;
    float *qb, *kb, *offp;
    cudaGetSymbolAddress((void**)&abig,  g_abig);
    cudaGetSymbolAddress((void**)&abig2, g_abig2);
    cudaGetSymbolAddress((void**)&bq_op, g_bop_q);
    cudaGetSymbolAddress((void**)&bk_op, g_bop_k);
    cudaGetSymbolAddress((void**)&bo_op, g_bop_o);
    cudaGetSymbolAddress((void**)&bf_op, g_bop_f);
    cudaGetSymbolAddress((void**)&qb,    g_q);
    cudaGetSymbolAddress((void**)&kb,    g_k);
    cudaGetSymbolAddress((void**)&offp,  g_offp);

    cudaFuncSetAttribute(gemm3, cudaFuncAttributeMaxDynamicSharedMemorySize, SMEM_SZ);
    cudaFuncSetAttribute(gemm_hmma, cudaFuncAttributeMaxDynamicSharedMemorySize, SMEM_SZ);

    // 1. all weight conversions in one launch
    conv_w4<<<dim3(32, 32, 4), dim3(32, 8)>>>(Wq, Wkv, Wout, Woff,
                                              bq_op, bk_op, bo_op, bf_op);

    // 2. both activation conversions in one launch
    const int cablk = (int)(((size_t)MM * 128 + 255) / 256);
    conv_act2<<<dim3(cablk, 2), 256>>>(query, ref, abig, abig2);

    // 3. q, k, off GEMMs in one launch (17*86 = 1462 CTAs)
    gemm3<<<17 * MTILES, 256, SMEM_SZ>>>(abig, abig2, bq_op, bk_op, bf_op,
                                         bq, bkv, boff, qb, kb, offp);

    // 4. sampling + attention; writes bf16 split operand into abig
    {
        int warps = MM * NHEADS;
        int blocks = (warps * 32 + 255) / 256;
        sample_attn_kernel<<<blocks, 256>>>(qb, kb, offp, abig);
    }

    // 5. out = attn @ Wout + bout
    gemm_hmma<<<dim3(8, MTILES), 256, SMEM_SZ>>>(abig, bo_op, bout, outp);
}

// round 7
// speedup vs baseline: 1.8155x; 1.2992x over previous
#include <cuda_runtime.h>
#include <cuda_fp16.h>
#include <cuda_bf16.h>
#include <math.h>
#include <cstdint>

// Problem constants
#define BB 8
#define HH 37
#define WW 37
#define NN (HH * WW)          // 1369
#define CC 1024
#define MM (BB * NN)          // 10952
#define NHEADS 8
#define HD 128
#define NPTS 8
#define K2 2048               // 2-term fp16 split: A=[Ah|Al], B=[Bh|Bh]
#define K3 3072               // 3-term (off GEMM): A=[Ah|Al|Ah], B=[Bh|Bh|Bl]
#define NCK2 (K2 / 64)        // 32
#define NCK3 (K3 / 64)        // 48
#define STAGES 3
#define STAGE_BYTES 32768     // A 16K + B 16K
#define SMEM_SZ (STAGES * STAGE_BYTES)
#define MTILES 86             // ceil(MM/128)

// ---------------------------------------------------------------------------
// Scratch
// ---------------------------------------------------------------------------
__device__ __half g_aq[MM * K3];      // query split [Ah|Al|Ah] (q uses K2 prefix, off uses K3)
__device__ __half g_ak[MM * K2];      // ref split [Ah|Al]; reused for attn split
__device__ __half g_bop_q[CC * K2];
__device__ __half g_bop_k[CC * K2];
__device__ __half g_bop_o[CC * K2];
__device__ __half g_bop_f[128 * K3];
__device__ float g_q[MM * CC];
__device__ float g_k[MM * CC];
__device__ float g_offp[MM * 128];

// ---------------------------------------------------------------------------
__device__ __forceinline__ uint32_t smem_u32(const void* p) {
    uint32_t a;
    asm("{ .reg .u64 t; cvta.to.shared.u64 t, %1; cvt.u32.u64 %0, t; }" : "=r"(a) : "l"(p));
    return a;
}
__device__ __forceinline__ void cp16(uint32_t dst, const void* src, bool valid) {
    int sz = valid ? 16 : 0;
    asm volatile("cp.async.cg.shared.global [%0], [%1], 16, %2;"
                 :: "r"(dst), "l"(src), "r"(sz) : "memory");
}
#define CP_COMMIT() asm volatile("cp.async.commit_group;" ::: "memory")
#define CP_WAIT1()  asm volatile("cp.async.wait_group 1;" ::: "memory")

__device__ __forceinline__ void ldsm4(uint32_t* r, uint32_t addr) {
    asm volatile("ldmatrix.sync.aligned.m8n8.x4.shared.b16 {%0,%1,%2,%3}, [%4];"
                 : "=r"(r[0]), "=r"(r[1]), "=r"(r[2]), "=r"(r[3]) : "r"(addr));
}
__device__ __forceinline__ void mma16816(float* c, const uint32_t* a, const uint32_t* b) {
    asm volatile(
        "mma.sync.aligned.m16n8k16.row.col.f32.f16.f16.f32 "
        "{%0,%1,%2,%3},{%4,%5,%6,%7},{%8,%9},{%0,%1,%2,%3};"
        : "+f"(c[0]), "+f"(c[1]), "+f"(c[2]), "+f"(c[3])
        : "r"(a[0]), "r"(a[1]), "r"(a[2]), "r"(a[3]), "r"(b[0]), "r"(b[1]));
}

// ---------------------------------------------------------------------------
// GEMM body: CTA 128x128, 8 warps 64x32, 3-stage cp.async. Variable K (nchunk).
// ---------------------------------------------------------------------------
__device__ __forceinline__
void gemm_body(const __half* __restrict__ A, int lda,
               const __half* __restrict__ B, int ldb,
               const float* __restrict__ bias, float* __restrict__ C,
               int ldc, int m0, int col0, int nchunk, char* smem) {
    const uint32_t sb0 = smem_u32(smem);
    const int tid = threadIdx.x, wid = tid >> 5, lane = tid & 31;
    const __half* Bc0 = B + (size_t)col0 * ldb;

    auto load_stage = [&](int ck, int stage) {
        const uint32_t sa = sb0 + stage * STAGE_BYTES;
        const __half* Ac = A + ck * 64;
        const __half* Bc = Bc0 + ck * 64;
#pragma unroll
        for (int i = 0; i < 4; i++) {
            int id = tid + i * 256;
            int row = id >> 3, c16 = id & 7;
            int gr = m0 + row;
            bool v = gr < MM;
            int grc = v ? gr : (MM - 1);
            uint32_t dst = sa + row * 128 + (((uint32_t)c16 ^ (row & 7)) << 4);
            cp16(dst, Ac + (size_t)grc * lda + c16 * 8, v);
        }
#pragma unroll
        for (int i = 0; i < 4; i++) {
            int id = tid + i * 256;
            int row = id >> 3, c16 = id & 7;
            uint32_t dst = sa + 16384 + row * 128 + (((uint32_t)c16 ^ (row & 7)) << 4);
            cp16(dst, Bc + (size_t)row * ldb + c16 * 8, true);
        }
        CP_COMMIT();
    };

    float acc[4][4][4];
#pragma unroll
    for (int mt = 0; mt < 4; mt++)
#pragma unroll
        for (int nt = 0; nt < 4; nt++)
#pragma unroll
            for (int j = 0; j < 4; j++) acc[mt][nt][j] = 0.0f;

    load_stage(0, 0);
    load_stage(1, 1);

    const int wm = (wid & 1) * 64;
    const int wn = (wid >> 1) * 32;

    for (int c = 0; c < nchunk; c++) {
        CP_WAIT1();
        __syncthreads();
        if (c + 2 < nchunk) load_stage(c + 2, (c + 2) % STAGES);
        else CP_COMMIT();

        const uint32_t sa = sb0 + (c % STAGES) * STAGE_BYTES;
        const uint32_t sbB = sa + 16384;

#pragma unroll
        for (int ks = 0; ks < 4; ks++) {
            uint32_t af[4][4];
#pragma unroll
            for (int mt = 0; mt < 4; mt++) {
                int row = wm + mt * 16 + (lane & 15);
                uint32_t c16 = (uint32_t)(ks * 2 + (lane >> 4)) ^ (row & 7);
                ldsm4(af[mt], sa + row * 128 + (c16 << 4));
            }
            uint32_t bf[4][2];
#pragma unroll
            for (int nt2 = 0; nt2 < 2; nt2++) {
                int group = lane >> 3;
                int nrow = wn + nt2 * 16 + (group >> 1) * 8 + (lane & 7);
                uint32_t c16 = (uint32_t)(ks * 2 + (group & 1)) ^ (nrow & 7);
                uint32_t r[4];
                ldsm4(r, sbB + nrow * 128 + (c16 << 4));
                bf[nt2 * 2][0] = r[0]; bf[nt2 * 2][1] = r[1];
                bf[nt2 * 2 + 1][0] = r[2]; bf[nt2 * 2 + 1][1] = r[3];
            }
#pragma unroll
            for (int mt = 0; mt < 4; mt++)
#pragma unroll
                for (int nt = 0; nt < 4; nt++)
                    mma16816(acc[mt][nt], af[mt], bf[nt]);
        }
        __syncthreads();
    }

    const int lr = lane >> 2, lc = (lane & 3) * 2;
#pragma unroll
    for (int mt = 0; mt < 4; mt++) {
#pragma unroll
        for (int nt = 0; nt < 4; nt++) {
            int r0 = m0 + wm + mt * 16 + lr;
            int cb = col0 + wn + nt * 8 + lc;
            float b0 = bias[cb], b1 = bias[cb + 1];
            if (r0 < MM) {
                float2 v = make_float2(acc[mt][nt][0] + b0, acc[mt][nt][1] + b1);
                *reinterpret_cast<float2*>(C + (size_t)r0 * ldc + cb) = v;
            }
            int r1 = r0 + 8;
            if (r1 < MM) {
                float2 v = make_float2(acc[mt][nt][2] + b0, acc[mt][nt][3] + b1);
                *reinterpret_cast<float2*>(C + (size_t)r1 * ldc + cb) = v;
            }
        }
    }
}

// Merged q + k + off GEMM launch. t = bx / MTILES:
// t == 0: off (K3, longest -> scheduled first); t in [1,9): q; t in [9,17): k.
__global__ __launch_bounds__(256)
void gemm3(const __half* __restrict__ Aq, const __half* __restrict__ Ak,
           const __half* __restrict__ Bq, const __half* __restrict__ Bk,
           const __half* __restrict__ Bf,
           const float* __restrict__ bq, const float* __restrict__ bkv,
           const float* __restrict__ boff,
           float* __restrict__ Cq, float* __restrict__ Ck, float* __restrict__ Coff) {
    extern __shared__ char smem[];
    const int bx = blockIdx.x;
    const int t = bx / MTILES;
    const int m0 = (bx % MTILES) * 128;
    if (t == 0) {
        gemm_body(Aq, K3, Bf, K3, boff, Coff, 128, m0, 0, NCK3, smem);
    } else if (t < 9) {
        gemm_body(Aq, K3, Bq, K2, bq, Cq, CC, m0, (t - 1) * 128, NCK2, smem);
    } else {
        gemm_body(Ak, K2, Bk, K2, bkv, Ck, CC, m0, (t - 9) * 128, NCK2, smem);
    }
}

// Final GEMM: out = attn_split @ Wout + bout  (K2)
__global__ __launch_bounds__(256)
void gemm_hmma(const __half* __restrict__ A, const __half* __restrict__ B,
               const float* __restrict__ bias, float* __restrict__ C) {
    extern __shared__ char smem[];
    gemm_body(A, K2, B, K2, bias, C, CC, blockIdx.y * 128, blockIdx.x * 128, NCK2, smem);
}

// ---------------------------------------------------------------------------
// Merged activation conversion:
// y==0: query fp32 -> fp16 [Ah|Al|Ah] stride K3 ; y==1: ref -> [Ah|Al] stride K2
// ---------------------------------------------------------------------------
__global__ __launch_bounds__(256)
void conv_act2(const float* __restrict__ A0, const float* __restrict__ A1,
               __half* __restrict__ O0, __half* __restrict__ O1) {
    const bool three = (blockIdx.y == 0);
    const float* A = three ? A0 : A1;
    size_t i = (size_t)blockIdx.x * blockDim.x + threadIdx.x;
    if (i >= (size_t)MM * 128) return;
    size_t r = i >> 7;
    int c8 = (int)(i & 127) * 8;
    const float4* p = reinterpret_cast<const float4*>(A + r * CC + c8);
    float4 v0 = p[0], v1 = p[1];
    float vv[8] = {v0.x, v0.y, v0.z, v0.w, v1.x, v1.y, v1.z, v1.w};
    __half hi[8], lo[8];
#pragma unroll
    for (int j = 0; j < 8; j++) {
        hi[j] = __float2half(vv[j]);
        lo[j] = __float2half(vv[j] - __half2float(hi[j]));
    }
    if (three) {
        __half* rp = O0 + r * K3;
        *reinterpret_cast<uint4*>(rp + c8)        = *reinterpret_cast<uint4*>(hi);
        *reinterpret_cast<uint4*>(rp + c8 + 1024) = *reinterpret_cast<uint4*>(lo);
        *reinterpret_cast<uint4*>(rp + c8 + 2048) = *reinterpret_cast<uint4*>(hi);
    } else {
        __half* rp = O1 + r * K2;
        *reinterpret_cast<uint4*>(rp + c8)        = *reinterpret_cast<uint4*>(hi);
        *reinterpret_cast<uint4*>(rp + c8 + 1024) = *reinterpret_cast<uint4*>(lo);
    }
}

// ---------------------------------------------------------------------------
// Merged weight conversion. z in {0,1,2}: [Bh|Bh] stride K2. z==3 (Woff):
// [Bh|Bh|Bl] stride K3.
// ---------------------------------------------------------------------------
__global__ __launch_bounds__(256)
void conv_w4(const float* __restrict__ W0, const float* __restrict__ W1,
             const float* __restrict__ W2, const float* __restrict__ W3,
             __half* __restrict__ O0, __half* __restrict__ O1,
             __half* __restrict__ O2, __half* __restrict__ O3) {
    const int z = blockIdx.z;
    const float* W;
    __half* Bop;
    int ldw, nvalid;
    if (z == 0)      { W = W0; Bop = O0; ldw = CC;     nvalid = CC; }
    else if (z == 1) { W = W1; Bop = O1; ldw = 2 * CC; nvalid = CC; }
    else if (z == 2) { W = W2; Bop = O2; ldw = CC;     nvalid = CC; }
    else             { W = W3; Bop = O3; ldw = 128;    nvalid = 128;
                       if (blockIdx.x >= 4) return; }

    __shared__ float t[32][33];
    const int n0 = blockIdx.x * 32, k0 = blockIdx.y * 32;
    const int tx = threadIdx.x, ty = threadIdx.y;
#pragma unroll
    for (int j = ty; j < 32; j += 8) {
        int n = n0 + tx, k = k0 + j;
        t[j][tx] = (n < nvalid) ? W[(size_t)k * ldw + n] : 0.0f;
    }
    __syncthreads();
#pragma unroll
    for (int j = ty; j < 32; j += 8) {
        int n = n0 + j, k = k0 + tx;
        float v = t[tx][j];
        __half h = __float2half(v);
        if (z < 3) {
            __half* row = Bop + (size_t)n * K2;
            row[k] = h; row[k + 1024] = h;
        } else {
            __half l = __float2half(v - __half2float(h));
            __half* row = Bop + (size_t)n * K3;
            row[k] = h; row[k + 1024] = h; row[k + 2048] = l;
        }
    }
}

// ---------------------------------------------------------------------------
// Sampling + attention. One warp per (b, n, head). off stride = 128.
// Writes fp16 split operand [Ah|Al] (stride K2) directly.
// ---------------------------------------------------------------------------
__global__ __launch_bounds__(256)
void sample_attn_kernel(const float* __restrict__ q, const float* __restrict__ k,
                        const float* __restrict__ off, __half* __restrict__ outop) {
    const int gwarp = (blockIdx.x * blockDim.x + threadIdx.x) >> 5;
    const int lane = threadIdx.x & 31;
    if (gwarp >= MM * NHEADS) return;

    const int h = gwarp & (NHEADS - 1);
    const int m = gwarp >> 3;
    const int n = m % NN;
    const int b = m / NN;

    const int ch = h * HD + lane * 4;
    float4 qv = *reinterpret_cast<const float4*>(q + (size_t)m * CC + ch);

    const int iy_n = n / WW;
    const int ix_n = n % WW;
    const float cy = -1.0f + 2.0f * (float)iy_n / (float)(HH - 1);
    const float cx = -1.0f + 2.0f * (float)ix_n / (float)(WW - 1);

    const float* offp = off + (size_t)m * 128 + h * (NPTS * 2);
    const float* kb = k + (size_t)b * NN * CC;

    float sk[NPTS][4];
    float score[NPTS];
    const float scale = 0.08838834764831845f;

#pragma unroll
    for (int p = 0; p < NPTS; p++) {
        float l0 = cy + offp[2 * p + 0];
        float l1 = cx + offp[2 * p + 1];
        float ix = (l0 + 1.0f) * 0.5f * (float)(WW - 1);
        float iy = (l1 + 1.0f) * 0.5f * (float)(HH - 1);
        ix = fminf(fmaxf(ix, 0.0f), (float)(WW - 1));
        iy = fminf(fmaxf(iy, 0.0f), (float)(HH - 1));
        float x0f = floorf(ix), y0f = floorf(iy);
        float wx = ix - x0f, wy = iy - y0f;
        int x0 = (int)x0f, y0 = (int)y0f;
        int x1 = min(x0 + 1, WW - 1);
        int y1 = min(y0 + 1, HH - 1);

        const float4 g00 = *reinterpret_cast<const float4*>(kb + (size_t)(y0 * WW + x0) * CC + ch);
        const float4 g01 = *reinterpret_cast<const float4*>(kb + (size_t)(y0 * WW + x1) * CC + ch);
        const float4 g10 = *reinterpret_cast<const float4*>(kb + (size_t)(y1 * WW + x0) * CC + ch);
        const float4 g11 = *reinterpret_cast<const float4*>(kb + (size_t)(y1 * WW + x1) * CC + ch);

        float w00 = (1.0f - wy) * (1.0f - wx);
        float w01 = (1.0f - wy) * wx;
        float w10 = wy * (1.0f - wx);
        float w11 = wy * wx;

        sk[p][0] = g00.x * w00 + g01.x * w01 + g10.x * w10 + g11.x * w11;
        sk[p][1] = g00.y * w00 + g01.y * w01 + g10.y * w10 + g11.y * w11;
        sk[p][2] = g00.z * w00 + g01.z * w01 + g10.z * w10 + g11.z * w11;
        sk[p][3] = g00.w * w00 + g01.w * w01 + g10.w * w10 + g11.w * w11;

        float s = qv.x * sk[p][0] + qv.y * sk[p][1] + qv.z * sk[p][2] + qv.w * sk[p][3];
#pragma unroll
        for (int d = 16; d > 0; d >>= 1)
            s += __shfl_xor_sync(0xFFFFFFFFu, s, d);
        score[p] = s * scale;
    }

    float mx = score[0];
#pragma unroll
    for (int p = 1; p < NPTS; p++) mx = fmaxf(mx, score[p]);
    float denom = 0.0f;
    float e[NPTS];
#pragma unroll
    for (int p = 0; p < NPTS; p++) { e[p] = expf(score[p] - mx); denom += e[p]; }
    float inv = 1.0f / denom;

    float av[4] = {0.f, 0.f, 0.f, 0.f};
#pragma unroll
    for (int p = 0; p < NPTS; p++) {
        float a = e[p] * inv;
        av[0] += a * sk[p][0];
        av[1] += a * sk[p][1];
        av[2] += a * sk[p][2];
        av[3] += a * sk[p][3];
    }

    __half hi[4], lo[4];
#pragma unroll
    for (int j = 0; j < 4; j++) {
        hi[j] = __float2half(av[j]);
        lo[j] = __float2half(av[j] - __half2float(hi[j]));
    }
    __half* rp = outop + (size_t)m * K2;
    *reinterpret_cast<uint2*>(rp + ch)        = *reinterpret_cast<uint2*>(hi);
    *reinterpret_cast<uint2*>(rp + ch + 1024) = *reinterpret_cast<uint2*>(lo);
}

// ---------------------------------------------------------------------------
extern "C" void kernel_launch(void* const* d_in, const int* in_sizes, int n_in,
                              void* d_out, int out_size) {
    const float* query = (const float*)d_in[0];
    const float* ref   = (const float*)d_in[1];
    const float* Wq    = (const float*)d_in[2];
    const float* bq    = (const float*)d_in[3];
    const float* Wkv   = (const float*)d_in[4];
    const float* bkv   = (const float*)d_in[5];
    const float* Woff  = (const float*)d_in[6];
    const float* boff  = (const float*)d_in[7];
    const float* Wout  = (const float*)d_in[8];
    const float* bout  = (const float*)d_in[9];
    float* outp = (float*)d_out;

    __half *aq, *ak, *bq_op, *bk_op, *bo_op, *bf_op;
    float *qb, *kb, *offp;
    cudaGetSymbolAddress((void**)&aq,    g_aq);
    cudaGetSymbolAddress((void**)&ak,    g_ak);
    cudaGetSymbolAddress((void**)&bq_op, g_bop_q);
    cudaGetSymbolAddress((void**)&bk_op, g_bop_k);
    cudaGetSymbolAddress((void**)&bo_op, g_bop_o);
    cudaGetSymbolAddress((void**)&bf_op, g_bop_f);
    cudaGetSymbolAddress((void**)&qb,    g_q);
    cudaGetSymbolAddress((void**)&kb,    g_k);
    cudaGetSymbolAddress((void**)&offp,  g_offp);

    cudaFuncSetAttribute(gemm3, cudaFuncAttributeMaxDynamicSharedMemorySize, SMEM_SZ);
    cudaFuncSetAttribute(gemm_hmma, cudaFuncAttributeMaxDynamicSharedMemorySize, SMEM_SZ);

    // 1. all weight conversions in one launch
    conv_w4<<<dim3(32, 32, 4), dim3(32, 8)>>>(Wq, Wkv, Wout, Woff,
                                              bq_op, bk_op, bo_op, bf_op);

    // 2. both activation conversions in one launch
    const int cablk = (int)(((size_t)MM * 128 + 255) / 256);
    conv_act2<<<dim3(cablk, 2), 256>>>(query, ref, aq, ak);

    // 3. off (K3) + q + k GEMMs in one launch (17*86 = 1462 CTAs, off first)
    gemm3<<<17 * MTILES, 256, SMEM_SZ>>>(aq, ak, bq_op, bk_op, bf_op,
                                         bq, bkv, boff, qb, kb, offp);

    // 4. sampling + attention; writes fp16 [Ah|Al] operand into ak (reuse)
    {
        int warps = MM * NHEADS;
        int blocks = (warps * 32 + 255) / 256;
        sample_attn_kernel<<<blocks, 256>>>(qb, kb, offp, ak);
    }

    // 5. out = attn @ Wout + bout  (K2)
    gemm_hmma<<<dim3(8, MTILES), 256, SMEM_SZ>>>(ak, bo_op, bout, outp);
}

// round 8
// speedup vs baseline: 2.3873x; 1.3149x over previous
#include <cuda_runtime.h>
#include <cuda_fp16.h>
#include <math.h>
#include <cstdint>

// Problem constants
#define BB 8
#define HH 37
#define WW 37
#define NN (HH * WW)          // 1369
#define CC 1024
#define MM (BB * NN)          // 10952
#define NHEADS 8
#define HD 128
#define NPTS 8
#define K1 1024               // 1-term fp16 (q, k GEMMs)
#define K2 2048               // 2-term fp16 (out GEMM)
#define K3 3072               // 3-term fp16 (off GEMM)
#define NCK1 (K1 / 64)        // 16
#define NCK2 (K2 / 64)        // 32
#define NCK3 (K3 / 64)        // 48
#define STAGES 3
#define STAGE_BYTES 32768     // A 16K + B 16K
#define SMEM_SZ (STAGES * STAGE_BYTES)
#define MTILES 86             // ceil(MM/128)
#define ACT_BLKS 5476         // MM*128/256

// ---------------------------------------------------------------------------
// Scratch
// ---------------------------------------------------------------------------
__device__ __half g_aq[MM * K3];      // query [Ah|Al|Ah]; later attn [Ah|Al] (K2 prefix)
__device__ __half g_ak[MM * K1];      // ref [Ah]
__device__ __half g_bop_q[CC * K1];   // Wq [Bh]
__device__ __half g_bop_k[CC * K1];   // Wkv[:, :C] [Bh]
__device__ __half g_bop_o[CC * K2];   // Wout [Bh|Bh]
__device__ __half g_bop_f[128 * K3];  // Woff [Bh|Bh|Bl]
__device__ float  g_q[MM * CC];
__device__ __half g_k[MM * CC];       // k output in fp16 (halves sampling traffic)
__device__ float  g_offp[MM * 128];

// ---------------------------------------------------------------------------
__device__ __forceinline__ uint32_t smem_u32(const void* p) {
    uint32_t a;
    asm("{ .reg .u64 t; cvta.to.shared.u64 t, %1; cvt.u32.u64 %0, t; }" : "=r"(a) : "l"(p));
    return a;
}
__device__ __forceinline__ void cp16(uint32_t dst, const void* src, bool valid) {
    int sz = valid ? 16 : 0;
    asm volatile("cp.async.cg.shared.global [%0], [%1], 16, %2;"
                 :: "r"(dst), "l"(src), "r"(sz) : "memory");
}
#define CP_COMMIT() asm volatile("cp.async.commit_group;" ::: "memory")
#define CP_WAIT1()  asm volatile("cp.async.wait_group 1;" ::: "memory")

__device__ __forceinline__ void ldsm4(uint32_t* r, uint32_t addr) {
    asm volatile("ldmatrix.sync.aligned.m8n8.x4.shared.b16 {%0,%1,%2,%3}, [%4];"
                 : "=r"(r[0]), "=r"(r[1]), "=r"(r[2]), "=r"(r[3]) : "r"(addr));
}
__device__ __forceinline__ void mma16816(float* c, const uint32_t* a, const uint32_t* b) {
    asm volatile(
        "mma.sync.aligned.m16n8k16.row.col.f32.f16.f16.f32 "
        "{%0,%1,%2,%3},{%4,%5,%6,%7},{%8,%9},{%0,%1,%2,%3};"
        : "+f"(c[0]), "+f"(c[1]), "+f"(c[2]), "+f"(c[3])
        : "r"(a[0]), "r"(a[1]), "r"(a[2]), "r"(a[3]), "r"(b[0]), "r"(b[1]));
}

// ---------------------------------------------------------------------------
// GEMM body: CTA 128x128, 8 warps 64x32, 3-stage cp.async. Templated output.
// ---------------------------------------------------------------------------
template <typename OutT>
__device__ __forceinline__
void gemm_body(const __half* __restrict__ A, int lda,
               const __half* __restrict__ B, int ldb,
               const float* __restrict__ bias, OutT* __restrict__ C,
               int ldc, int m0, int col0, int nchunk, char* smem) {
    const uint32_t sb0 = smem_u32(smem);
    const int tid = threadIdx.x, wid = tid >> 5, lane = tid & 31;
    const __half* Bc0 = B + (size_t)col0 * ldb;

    auto load_stage = [&](int ck, int stage) {
        const uint32_t sa = sb0 + stage * STAGE_BYTES;
        const __half* Ac = A + ck * 64;
        const __half* Bc = Bc0 + ck * 64;
#pragma unroll
        for (int i = 0; i < 4; i++) {
            int id = tid + i * 256;
            int row = id >> 3, c16 = id & 7;
            int gr = m0 + row;
            bool v = gr < MM;
            int grc = v ? gr : (MM - 1);
            uint32_t dst = sa + row * 128 + (((uint32_t)c16 ^ (row & 7)) << 4);
            cp16(dst, Ac + (size_t)grc * lda + c16 * 8, v);
        }
#pragma unroll
        for (int i = 0; i < 4; i++) {
            int id = tid + i * 256;
            int row = id >> 3, c16 = id & 7;
            uint32_t dst = sa + 16384 + row * 128 + (((uint32_t)c16 ^ (row & 7)) << 4);
            cp16(dst, Bc + (size_t)row * ldb + c16 * 8, true);
        }
        CP_COMMIT();
    };

    float acc[4][4][4];
#pragma unroll
    for (int mt = 0; mt < 4; mt++)
#pragma unroll
        for (int nt = 0; nt < 4; nt++)
#pragma unroll
            for (int j = 0; j < 4; j++) acc[mt][nt][j] = 0.0f;

    load_stage(0, 0);
    load_stage(1, 1);

    const int wm = (wid & 1) * 64;
    const int wn = (wid >> 1) * 32;

    for (int c = 0; c < nchunk; c++) {
        CP_WAIT1();
        __syncthreads();
        if (c + 2 < nchunk) load_stage(c + 2, (c + 2) % STAGES);
        else CP_COMMIT();

        const uint32_t sa = sb0 + (c % STAGES) * STAGE_BYTES;
        const uint32_t sbB = sa + 16384;

#pragma unroll
        for (int ks = 0; ks < 4; ks++) {
            uint32_t af[4][4];
#pragma unroll
            for (int mt = 0; mt < 4; mt++) {
                int row = wm + mt * 16 + (lane & 15);
                uint32_t c16 = (uint32_t)(ks * 2 + (lane >> 4)) ^ (row & 7);
                ldsm4(af[mt], sa + row * 128 + (c16 << 4));
            }
            uint32_t bf[4][2];
#pragma unroll
            for (int nt2 = 0; nt2 < 2; nt2++) {
                int group = lane >> 3;
                int nrow = wn + nt2 * 16 + (group >> 1) * 8 + (lane & 7);
                uint32_t c16 = (uint32_t)(ks * 2 + (group & 1)) ^ (nrow & 7);
                uint32_t r[4];
                ldsm4(r, sbB + nrow * 128 + (c16 << 4));
                bf[nt2 * 2][0] = r[0]; bf[nt2 * 2][1] = r[1];
                bf[nt2 * 2 + 1][0] = r[2]; bf[nt2 * 2 + 1][1] = r[3];
            }
#pragma unroll
            for (int mt = 0; mt < 4; mt++)
#pragma unroll
                for (int nt = 0; nt < 4; nt++)
                    mma16816(acc[mt][nt], af[mt], bf[nt]);
        }
        __syncthreads();
    }

    const int lr = lane >> 2, lc = (lane & 3) * 2;
#pragma unroll
    for (int mt = 0; mt < 4; mt++) {
#pragma unroll
        for (int nt = 0; nt < 4; nt++) {
            int r0 = m0 + wm + mt * 16 + lr;
            int cb = col0 + wn + nt * 8 + lc;
            float b0 = bias[cb], b1 = bias[cb + 1];
            if (r0 < MM) {
                if (sizeof(OutT) == 2) {
                    __half2 v = __floats2half2_rn(acc[mt][nt][0] + b0, acc[mt][nt][1] + b1);
                    *reinterpret_cast<__half2*>((__half*)C + (size_t)r0 * ldc + cb) = v;
                } else {
                    float2 v = make_float2(acc[mt][nt][0] + b0, acc[mt][nt][1] + b1);
                    *reinterpret_cast<float2*>((float*)C + (size_t)r0 * ldc + cb) = v;
                }
            }
            int r1 = r0 + 8;
            if (r1 < MM) {
                if (sizeof(OutT) == 2) {
                    __half2 v = __floats2half2_rn(acc[mt][nt][2] + b0, acc[mt][nt][3] + b1);
                    *reinterpret_cast<__half2*>((__half*)C + (size_t)r1 * ldc + cb) = v;
                } else {
                    float2 v = make_float2(acc[mt][nt][2] + b0, acc[mt][nt][3] + b1);
                    *reinterpret_cast<float2*>((float*)C + (size_t)r1 * ldc + cb) = v;
                }
            }
        }
    }
}

// Merged off + q + k GEMM. t = bx / MTILES:
// t == 0: off (K3, longest, first); t in [1,9): q (K1); t in [9,17): k (K1, fp16 out).
__global__ __launch_bounds__(256)
void gemm3(const __half* __restrict__ Aq, const __half* __restrict__ Ak,
           const __half* __restrict__ Bq, const __half* __restrict__ Bk,
           const __half* __restrict__ Bf,
           const float* __restrict__ bq, const float* __restrict__ bkv,
           const float* __restrict__ boff,
           float* __restrict__ Cq, __half* __restrict__ Ck, float* __restrict__ Coff) {
    extern __shared__ char smem[];
    const int bx = blockIdx.x;
    const int t = bx / MTILES;
    const int m0 = (bx % MTILES) * 128;
    if (t == 0) {
        gemm_body<float>(Aq, K3, Bf, K3, boff, Coff, 128, m0, 0, NCK3, smem);
    } else if (t < 9) {
        gemm_body<float>(Aq, K3, Bq, K1, bq, Cq, CC, m0, (t - 1) * 128, NCK1, smem);
    } else {
        gemm_body<__half>(Ak, K1, Bk, K1, bkv, Ck, CC, m0, (t - 9) * 128, NCK1, smem);
    }
}

// Final GEMM: out = attn_split(K2) @ Wout + bout
__global__ __launch_bounds__(256)
void gemm_out(const __half* __restrict__ A, const __half* __restrict__ B,
              const float* __restrict__ bias, float* __restrict__ C) {
    extern __shared__ char smem[];
    gemm_body<float>(A, K2, B, K2, bias, C, CC, blockIdx.y * 128, blockIdx.x * 128, NCK2, smem);
}

// ---------------------------------------------------------------------------
// ALL conversions in one launch. Grid = 4096 (weights) + 2*ACT_BLKS (acts).
// ---------------------------------------------------------------------------
__global__ __launch_bounds__(256)
void conv_all(const float* __restrict__ Wq, const float* __restrict__ Wkv,
              const float* __restrict__ Wout, const float* __restrict__ Woff,
              __half* __restrict__ Oq, __half* __restrict__ Ok,
              __half* __restrict__ Oo, __half* __restrict__ Of,
              const float* __restrict__ query, const float* __restrict__ ref,
              __half* __restrict__ aq, __half* __restrict__ ak) {
    const int bid = blockIdx.x;
    if (bid < 4096) {
        // ---- weight transpose+split. 1024 blocks per weight (32 n x 32 k) ----
        const int z = bid >> 10, r = bid & 1023;
        const int nt = r & 31, kt = r >> 5;
        if (z == 3 && nt >= 4) return;
        const float* W;
        int ldw, nvalid;
        if (z == 0)      { W = Wq;   ldw = CC;     nvalid = CC; }
        else if (z == 1) { W = Wkv;  ldw = 2 * CC; nvalid = CC; }
        else if (z == 2) { W = Wout; ldw = CC;     nvalid = CC; }
        else             { W = Woff; ldw = 128;    nvalid = 128; }

        __shared__ float t[32][33];
        const int tx = threadIdx.x & 31, ty = threadIdx.x >> 5;
        const int n0 = nt * 32, k0 = kt * 32;
#pragma unroll
        for (int j = ty; j < 32; j += 8) {
            int n = n0 + tx, k = k0 + j;
            t[j][tx] = (n < nvalid) ? W[(size_t)k * ldw + n] : 0.0f;
        }
        __syncthreads();
#pragma unroll
        for (int j = ty; j < 32; j += 8) {
            int n = n0 + j, k = k0 + tx;
            float v = t[tx][j];
            __half h = __float2half(v);
            if (z == 0)      { Oq[(size_t)n * K1 + k] = h; }
            else if (z == 1) { Ok[(size_t)n * K1 + k] = h; }
            else if (z == 2) { __half* row = Oo + (size_t)n * K2;
                               row[k] = h; row[k + 1024] = h; }
            else             { __half l = __float2half(v - __half2float(h));
                               __half* row = Of + (size_t)n * K3;
                               row[k] = h; row[k + 1024] = h; row[k + 2048] = l; }
        }
    } else {
        // ---- activation conversion ----
        const int j = bid - 4096;
        const bool isq = j < ACT_BLKS;
        const int blk = isq ? j : j - ACT_BLKS;
        size_t i = (size_t)blk * 256 + threadIdx.x;
        if (i >= (size_t)MM * 128) return;
        size_t rrow = i >> 7;
        int c8 = (int)(i & 127) * 8;
        const float* A = isq ? query : ref;
        const float4* p = reinterpret_cast<const float4*>(A + rrow * CC + c8);
        float4 v0 = p[0], v1 = p[1];
        float vv[8] = {v0.x, v0.y, v0.z, v0.w, v1.x, v1.y, v1.z, v1.w};
        __half hi[8], lo[8];
#pragma unroll
        for (int jj = 0; jj < 8; jj++) {
            hi[jj] = __float2half(vv[jj]);
            lo[jj] = __float2half(vv[jj] - __half2float(hi[jj]));
        }
        if (isq) {  // query: [Ah|Al|Ah] stride K3 (off GEMM uses K3, q GEMM the K1 prefix)
            __half* rp = aq + rrow * K3;
            *reinterpret_cast<uint4*>(rp + c8)        = *reinterpret_cast<uint4*>(hi);
            *reinterpret_cast<uint4*>(rp + c8 + 1024) = *reinterpret_cast<uint4*>(lo);
            *reinterpret_cast<uint4*>(rp + c8 + 2048) = *reinterpret_cast<uint4*>(hi);
        } else {    // ref: [Ah] stride K1
            __half* rp = ak + rrow * K1;
            *reinterpret_cast<uint4*>(rp + c8) = *reinterpret_cast<uint4*>(hi);
        }
    }
}

// ---------------------------------------------------------------------------
// Sampling + attention. One warp per (b, n, head). k is fp16 (half traffic).
// Writes fp16 attn operand [Ah|Al] (stride K2) directly.
// ---------------------------------------------------------------------------
__global__ __launch_bounds__(256)
void sample_attn_kernel(const float* __restrict__ q, const __half* __restrict__ k,
                        const float* __restrict__ off, __half* __restrict__ outop) {
    const int gwarp = (blockIdx.x * blockDim.x + threadIdx.x) >> 5;
    const int lane = threadIdx.x & 31;
    if (gwarp >= MM * NHEADS) return;

    const int h = gwarp & (NHEADS - 1);
    const int m = gwarp >> 3;
    const int n = m % NN;
    const int b = m / NN;

    const int ch = h * HD + lane * 4;
    float4 qv = *reinterpret_cast<const float4*>(q + (size_t)m * CC + ch);

    const int iy_n = n / WW;
    const int ix_n = n % WW;
    const float cy = -1.0f + 2.0f * (float)iy_n / (float)(HH - 1);
    const float cx = -1.0f + 2.0f * (float)ix_n / (float)(WW - 1);

    const float* offp = off + (size_t)m * 128 + h * (NPTS * 2);
    const __half* kb = k + (size_t)b * NN * CC;

    float sk[NPTS][4];
    float score[NPTS];
    const float scale = 0.08838834764831845f;

#pragma unroll
    for (int p = 0; p < NPTS; p++) {
        float l0 = cy + offp[2 * p + 0];
        float l1 = cx + offp[2 * p + 1];
        float ix = (l0 + 1.0f) * 0.5f * (float)(WW - 1);
        float iy = (l1 + 1.0f) * 0.5f * (float)(HH - 1);
        ix = fminf(fmaxf(ix, 0.0f), (float)(WW - 1));
        iy = fminf(fmaxf(iy, 0.0f), (float)(HH - 1));
        float x0f = floorf(ix), y0f = floorf(iy);
        float wx = ix - x0f, wy = iy - y0f;
        int x0 = (int)x0f, y0 = (int)y0f;
        int x1 = min(x0 + 1, WW - 1);
        int y1 = min(y0 + 1, HH - 1);

        const __half2* p00 = reinterpret_cast<const __half2*>(kb + (size_t)(y0 * WW + x0) * CC + ch);
        const __half2* p01 = reinterpret_cast<const __half2*>(kb + (size_t)(y0 * WW + x1) * CC + ch);
        const __half2* p10 = reinterpret_cast<const __half2*>(kb + (size_t)(y1 * WW + x0) * CC + ch);
        const __half2* p11 = reinterpret_cast<const __half2*>(kb + (size_t)(y1 * WW + x1) * CC + ch);
        float2 a00 = __half22float2(p00[0]), b00 = __half22float2(p00[1]);
        float2 a01 = __half22float2(p01[0]), b01 = __half22float2(p01[1]);
        float2 a10 = __half22float2(p10[0]), b10 = __half22float2(p10[1]);
        float2 a11 = __half22float2(p11[0]), b11 = __half22float2(p11[1]);

        float w00 = (1.0f - wy) * (1.0f - wx);
        float w01 = (1.0f - wy) * wx;
        float w10 = wy * (1.0f - wx);
        float w11 = wy * wx;

        sk[p][0] = a00.x * w00 + a01.x * w01 + a10.x * w10 + a11.x * w11;
        sk[p][1] = a00.y * w00 + a01.y * w01 + a10.y * w10 + a11.y * w11;
        sk[p][2] = b00.x * w00 + b01.x * w01 + b10.x * w10 + b11.x * w11;
        sk[p][3] = b00.y * w00 + b01.y * w01 + b10.y * w10 + b11.y * w11;

        float s = qv.x * sk[p][0] + qv.y * sk[p][1] + qv.z * sk[p][2] + qv.w * sk[p][3];
#pragma unroll
        for (int d = 16; d > 0; d >>= 1)
            s += __shfl_xor_sync(0xFFFFFFFFu, s, d);
        score[p] = s * scale;
    }

    float mx = score[0];
#pragma unroll
    for (int p = 1; p < NPTS; p++) mx = fmaxf(mx, score[p]);
    float denom = 0.0f;
    float e[NPTS];
#pragma unroll
    for (int p = 0; p < NPTS; p++) { e[p] = __expf(score[p] - mx); denom += e[p]; }
    float inv = 1.0f / denom;

    float av[4] = {0.f, 0.f, 0.f, 0.f};
#pragma unroll
    for (int p = 0; p < NPTS; p++) {
        float a = e[p] * inv;
        av[0] += a * sk[p][0];
        av[1] += a * sk[p][1];
        av[2] += a * sk[p][2];
        av[3] += a * sk[p][3];
    }

    __half hi[4], lo[4];
#pragma unroll
    for (int j = 0; j < 4; j++) {
        hi[j] = __float2half(av[j]);
        lo[j] = __float2half(av[j] - __half2float(hi[j]));
    }
    __half* rp = outop + (size_t)m * K2;
    *reinterpret_cast<uint2*>(rp + ch)        = *reinterpret_cast<uint2*>(hi);
    *reinterpret_cast<uint2*>(rp + ch + 1024) = *reinterpret_cast<uint2*>(lo);
}

// ---------------------------------------------------------------------------
extern "C" void kernel_launch(void* const* d_in, const int* in_sizes, int n_in,
                              void* d_out, int out_size) {
    const float* query = (const float*)d_in[0];
    const float* ref   = (const float*)d_in[1];
    const float* Wq    = (const float*)d_in[2];
    const float* bq    = (const float*)d_in[3];
    const float* Wkv   = (const float*)d_in[4];
    const float* bkv   = (const float*)d_in[5];
    const float* Woff  = (const float*)d_in[6];
    const float* boff  = (const float*)d_in[7];
    const float* Wout  = (const float*)d_in[8];
    const float* bout  = (const float*)d_in[9];
    float* outp = (float*)d_out;

    __half *aq, *ak, *bq_op, *bk_op, *bo_op, *bf_op, *kb;
    float *qb, *offp;
    cudaGetSymbolAddress((void**)&aq,    g_aq);
    cudaGetSymbolAddress((void**)&ak,    g_ak);
    cudaGetSymbolAddress((void**)&bq_op, g_bop_q);
    cudaGetSymbolAddress((void**)&bk_op, g_bop_k);
    cudaGetSymbolAddress((void**)&bo_op, g_bop_o);
    cudaGetSymbolAddress((void**)&bf_op, g_bop_f);
    cudaGetSymbolAddress((void**)&qb,    g_q);
    cudaGetSymbolAddress((void**)&kb,    g_k);
    cudaGetSymbolAddress((void**)&offp,  g_offp);

    cudaFuncSetAttribute(gemm3, cudaFuncAttributeMaxDynamicSharedMemorySize, SMEM_SZ);
    cudaFuncSetAttribute(gemm_out, cudaFuncAttributeMaxDynamicSharedMemorySize, SMEM_SZ);

    // 1. ALL conversions (weights + both activations) in one launch
    conv_all<<<4096 + 2 * ACT_BLKS, 256>>>(Wq, Wkv, Wout, Woff,
                                           bq_op, bk_op, bo_op, bf_op,
                                           query, ref, aq, ak);

    // 2. off (K3) + q (K1) + k (K1, fp16 out) in one launch
    gemm3<<<17 * MTILES, 256, SMEM_SZ>>>(aq, ak, bq_op, bk_op, bf_op,
                                         bq, bkv, boff, qb, kb, offp);

    // 3. sampling + attention; writes fp16 [Ah|Al] attn operand into aq (reuse)
    {
        int warps = MM * NHEADS;
        int blocks = (warps * 32 + 255) / 256;
        sample_attn_kernel<<<blocks, 256>>>(qb, kb, offp, aq);
    }

    // 4. out = attn @ Wout + bout  (K2)
    gemm_out<<<dim3(8, MTILES), 256, SMEM_SZ>>>(aq, bo_op, bout, outp);
}

// round 9
// speedup vs baseline: 2.7662x; 1.1587x over previous
#include <cuda_runtime.h>
#include <cuda_fp16.h>
#include <math.h>
#include <cstdint>

// Problem constants
#define BB 8
#define HH 37
#define WW 37
#define NN (HH * WW)          // 1369
#define CC 1024
#define MM (BB * NN)          // 10952
#define NHEADS 8
#define HD 128
#define NPTS 8
#define K1 1024               // 1-term fp16 (q, k, out GEMMs)
#define K3 3072               // 3-term fp16 (off GEMM only)
#define NCK1 (K1 / 64)        // 16
#define NCK3 (K3 / 64)        // 48
#define STAGES 3
#define STAGE_BYTES 32768     // A 16K + B 16K
#define SMEM_SZ (STAGES * STAGE_BYTES)
#define MTILES 86             // ceil(MM/128)
#define ACT_BLKS 5476         // MM*128/256

// ---------------------------------------------------------------------------
// Scratch
// ---------------------------------------------------------------------------
__device__ __half g_aq[MM * K3];      // query [Ah|Al|Ah] (off uses K3, q the K1 prefix)
__device__ __half g_ak[MM * K1];      // ref [Ah]; reused as attn [Ah]
__device__ __half g_bop_q[CC * K1];   // Wq [Bh]
__device__ __half g_bop_k[CC * K1];   // Wkv[:, :C] [Bh]
__device__ __half g_bop_o[CC * K1];   // Wout [Bh]
__device__ __half g_bop_f[128 * K3];  // Woff [Bh|Bh|Bl]
__device__ __half g_q[MM * CC];       // q in fp16
__device__ __half g_k[MM * CC];       // k in fp16
__device__ float  g_offp[MM * 128];

// ---------------------------------------------------------------------------
__device__ __forceinline__ uint32_t smem_u32(const void* p) {
    uint32_t a;
    asm("{ .reg .u64 t; cvta.to.shared.u64 t, %1; cvt.u32.u64 %0, t; }" : "=r"(a) : "l"(p));
    return a;
}
__device__ __forceinline__ void cp16(uint32_t dst, const void* src, bool valid) {
    int sz = valid ? 16 : 0;
    asm volatile("cp.async.cg.shared.global [%0], [%1], 16, %2;"
                 :: "r"(dst), "l"(src), "r"(sz) : "memory");
}
#define CP_COMMIT() asm volatile("cp.async.commit_group;" ::: "memory")
#define CP_WAIT1()  asm volatile("cp.async.wait_group 1;" ::: "memory")

__device__ __forceinline__ void ldsm4(uint32_t* r, uint32_t addr) {
    asm volatile("ldmatrix.sync.aligned.m8n8.x4.shared.b16 {%0,%1,%2,%3}, [%4];"
                 : "=r"(r[0]), "=r"(r[1]), "=r"(r[2]), "=r"(r[3]) : "r"(addr));
}
__device__ __forceinline__ void mma16816(float* c, const uint32_t* a, const uint32_t* b) {
    asm volatile(
        "mma.sync.aligned.m16n8k16.row.col.f32.f16.f16.f32 "
        "{%0,%1,%2,%3},{%4,%5,%6,%7},{%8,%9},{%0,%1,%2,%3};"
        : "+f"(c[0]), "+f"(c[1]), "+f"(c[2]), "+f"(c[3])
        : "r"(a[0]), "r"(a[1]), "r"(a[2]), "r"(a[3]), "r"(b[0]), "r"(b[1]));
}

// ---------------------------------------------------------------------------
// GEMM body: CTA 128x128, 8 warps 64x32, 3-stage cp.async. Templated output.
// ---------------------------------------------------------------------------
template <typename OutT>
__device__ __forceinline__
void gemm_body(const __half* __restrict__ A, int lda,
               const __half* __restrict__ B, int ldb,
               const float* __restrict__ bias, OutT* __restrict__ C,
               int ldc, int m0, int col0, int nchunk, char* smem) {
    const uint32_t sb0 = smem_u32(smem);
    const int tid = threadIdx.x, wid = tid >> 5, lane = tid & 31;
    const __half* Bc0 = B + (size_t)col0 * ldb;

    auto load_stage = [&](int ck, int stage) {
        const uint32_t sa = sb0 + stage * STAGE_BYTES;
        const __half* Ac = A + ck * 64;
        const __half* Bc = Bc0 + ck * 64;
#pragma unroll
        for (int i = 0; i < 4; i++) {
            int id = tid + i * 256;
            int row = id >> 3, c16 = id & 7;
            int gr = m0 + row;
            bool v = gr < MM;
            int grc = v ? gr : (MM - 1);
            uint32_t dst = sa + row * 128 + (((uint32_t)c16 ^ (row & 7)) << 4);
            cp16(dst, Ac + (size_t)grc * lda + c16 * 8, v);
        }
#pragma unroll
        for (int i = 0; i < 4; i++) {
            int id = tid + i * 256;
            int row = id >> 3, c16 = id & 7;
            uint32_t dst = sa + 16384 + row * 128 + (((uint32_t)c16 ^ (row & 7)) << 4);
            cp16(dst, Bc + (size_t)row * ldb + c16 * 8, true);
        }
        CP_COMMIT();
    };

    float acc[4][4][4];
#pragma unroll
    for (int mt = 0; mt < 4; mt++)
#pragma unroll
        for (int nt = 0; nt < 4; nt++)
#pragma unroll
            for (int j = 0; j < 4; j++) acc[mt][nt][j] = 0.0f;

    load_stage(0, 0);
    load_stage(1, 1);

    const int wm = (wid & 1) * 64;
    const int wn = (wid >> 1) * 32;

    for (int c = 0; c < nchunk; c++) {
        CP_WAIT1();
        __syncthreads();
        if (c + 2 < nchunk) load_stage(c + 2, (c + 2) % STAGES);
        else CP_COMMIT();

        const uint32_t sa = sb0 + (c % STAGES) * STAGE_BYTES;
        const uint32_t sbB = sa + 16384;

#pragma unroll
        for (int ks = 0; ks < 4; ks++) {
            uint32_t af[4][4];
#pragma unroll
            for (int mt = 0; mt < 4; mt++) {
                int row = wm + mt * 16 + (lane & 15);
                uint32_t c16 = (uint32_t)(ks * 2 + (lane >> 4)) ^ (row & 7);
                ldsm4(af[mt], sa + row * 128 + (c16 << 4));
            }
            uint32_t bf[4][2];
#pragma unroll
            for (int nt2 = 0; nt2 < 2; nt2++) {
                int group = lane >> 3;
                int nrow = wn + nt2 * 16 + (group >> 1) * 8 + (lane & 7);
                uint32_t c16 = (uint32_t)(ks * 2 + (group & 1)) ^ (nrow & 7);
                uint32_t r[4];
                ldsm4(r, sbB + nrow * 128 + (c16 << 4));
                bf[nt2 * 2][0] = r[0]; bf[nt2 * 2][1] = r[1];
                bf[nt2 * 2 + 1][0] = r[2]; bf[nt2 * 2 + 1][1] = r[3];
            }
#pragma unroll
            for (int mt = 0; mt < 4; mt++)
#pragma unroll
                for (int nt = 0; nt < 4; nt++)
                    mma16816(acc[mt][nt], af[mt], bf[nt]);
        }
        __syncthreads();
    }

    const int lr = lane >> 2, lc = (lane & 3) * 2;
#pragma unroll
    for (int mt = 0; mt < 4; mt++) {
#pragma unroll
        for (int nt = 0; nt < 4; nt++) {
            int r0 = m0 + wm + mt * 16 + lr;
            int cb = col0 + wn + nt * 8 + lc;
            float b0 = bias[cb], b1 = bias[cb + 1];
            if (r0 < MM) {
                if (sizeof(OutT) == 2) {
                    __half2 v = __floats2half2_rn(acc[mt][nt][0] + b0, acc[mt][nt][1] + b1);
                    *reinterpret_cast<__half2*>((__half*)C + (size_t)r0 * ldc + cb) = v;
                } else {
                    float2 v = make_float2(acc[mt][nt][0] + b0, acc[mt][nt][1] + b1);
                    *reinterpret_cast<float2*>((float*)C + (size_t)r0 * ldc + cb) = v;
                }
            }
            int r1 = r0 + 8;
            if (r1 < MM) {
                if (sizeof(OutT) == 2) {
                    __half2 v = __floats2half2_rn(acc[mt][nt][2] + b0, acc[mt][nt][3] + b1);
                    *reinterpret_cast<__half2*>((__half*)C + (size_t)r1 * ldc + cb) = v;
                } else {
                    float2 v = make_float2(acc[mt][nt][2] + b0, acc[mt][nt][3] + b1);
                    *reinterpret_cast<float2*>((float*)C + (size_t)r1 * ldc + cb) = v;
                }
            }
        }
    }
}

// Merged off + q + k GEMM. t = bx / MTILES:
// t == 0: off (K3, longest, first); t in [1,9): q (fp16 out); t in [9,17): k (fp16 out).
__global__ __launch_bounds__(256)
void gemm3(const __half* __restrict__ Aq, const __half* __restrict__ Ak,
           const __half* __restrict__ Bq, const __half* __restrict__ Bk,
           const __half* __restrict__ Bf,
           const float* __restrict__ bq, const float* __restrict__ bkv,
           const float* __restrict__ boff,
           __half* __restrict__ Cq, __half* __restrict__ Ck, float* __restrict__ Coff) {
    extern __shared__ char smem[];
    const int bx = blockIdx.x;
    const int t = bx / MTILES;
    const int m0 = (bx % MTILES) * 128;
    if (t == 0) {
        gemm_body<float>(Aq, K3, Bf, K3, boff, Coff, 128, m0, 0, NCK3, smem);
    } else if (t < 9) {
        gemm_body<__half>(Aq, K3, Bq, K1, bq, Cq, CC, m0, (t - 1) * 128, NCK1, smem);
    } else {
        gemm_body<__half>(Ak, K1, Bk, K1, bkv, Ck, CC, m0, (t - 9) * 128, NCK1, smem);
    }
}

// Final GEMM: out = attn(K1) @ Wout + bout
__global__ __launch_bounds__(256)
void gemm_out(const __half* __restrict__ A, const __half* __restrict__ B,
              const float* __restrict__ bias, float* __restrict__ C) {
    extern __shared__ char smem[];
    gemm_body<float>(A, K1, B, K1, bias, C, CC, blockIdx.y * 128, blockIdx.x * 128, NCK1, smem);
}

// ---------------------------------------------------------------------------
// ALL conversions in one launch. Grid = 4096 (weights) + 2*ACT_BLKS (acts).
// ---------------------------------------------------------------------------
__global__ __launch_bounds__(256)
void conv_all(const float* __restrict__ Wq, const float* __restrict__ Wkv,
              const float* __restrict__ Wout, const float* __restrict__ Woff,
              __half* __restrict__ Oq, __half* __restrict__ Ok,
              __half* __restrict__ Oo, __half* __restrict__ Of,
              const float* __restrict__ query, const float* __restrict__ ref,
              __half* __restrict__ aq, __half* __restrict__ ak) {
    const int bid = blockIdx.x;
    if (bid < 4096) {
        const int z = bid >> 10, r = bid & 1023;
        const int nt = r & 31, kt = r >> 5;
        if (z == 3 && nt >= 4) return;
        const float* W;
        int ldw, nvalid;
        if (z == 0)      { W = Wq;   ldw = CC;     nvalid = CC; }
        else if (z == 1) { W = Wkv;  ldw = 2 * CC; nvalid = CC; }
        else if (z == 2) { W = Wout; ldw = CC;     nvalid = CC; }
        else             { W = Woff; ldw = 128;    nvalid = 128; }

        __shared__ float t[32][33];
        const int tx = threadIdx.x & 31, ty = threadIdx.x >> 5;
        const int n0 = nt * 32, k0 = kt * 32;
#pragma unroll
        for (int j = ty; j < 32; j += 8) {
            int n = n0 + tx, k = k0 + j;
            t[j][tx] = (n < nvalid) ? W[(size_t)k * ldw + n] : 0.0f;
        }
        __syncthreads();
#pragma unroll
        for (int j = ty; j < 32; j += 8) {
            int n = n0 + j, k = k0 + tx;
            float v = t[tx][j];
            __half h = __float2half(v);
            if (z == 0)      { Oq[(size_t)n * K1 + k] = h; }
            else if (z == 1) { Ok[(size_t)n * K1 + k] = h; }
            else if (z == 2) { Oo[(size_t)n * K1 + k] = h; }
            else             { __half l = __float2half(v - __half2float(h));
                               __half* row = Of + (size_t)n * K3;
                               row[k] = h; row[k + 1024] = h; row[k + 2048] = l; }
        }
    } else {
        const int j = bid - 4096;
        const bool isq = j < ACT_BLKS;
        const int blk = isq ? j : j - ACT_BLKS;
        size_t i = (size_t)blk * 256 + threadIdx.x;
        if (i >= (size_t)MM * 128) return;
        size_t rrow = i >> 7;
        int c8 = (int)(i & 127) * 8;
        const float* A = isq ? query : ref;
        const float4* p = reinterpret_cast<const float4*>(A + rrow * CC + c8);
        float4 v0 = p[0], v1 = p[1];
        float vv[8] = {v0.x, v0.y, v0.z, v0.w, v1.x, v1.y, v1.z, v1.w};
        __half hi[8], lo[8];
#pragma unroll
        for (int jj = 0; jj < 8; jj++) {
            hi[jj] = __float2half(vv[jj]);
            lo[jj] = __float2half(vv[jj] - __half2float(hi[jj]));
        }
        if (isq) {  // query: [Ah|Al|Ah] stride K3
            __half* rp = aq + rrow * K3;
            *reinterpret_cast<uint4*>(rp + c8)        = *reinterpret_cast<uint4*>(hi);
            *reinterpret_cast<uint4*>(rp + c8 + 1024) = *reinterpret_cast<uint4*>(lo);
            *reinterpret_cast<uint4*>(rp + c8 + 2048) = *reinterpret_cast<uint4*>(hi);
        } else {    // ref: [Ah] stride K1
            __half* rp = ak + rrow * K1;
            *reinterpret_cast<uint4*>(rp + c8) = *reinterpret_cast<uint4*>(hi);
        }
    }
}

// ---------------------------------------------------------------------------
// Sampling + attention. One warp per (b, n, head). q, k fp16.
// Writes fp16 attn operand [Ah] (stride K1) directly.
// ---------------------------------------------------------------------------
__global__ __launch_bounds__(256)
void sample_attn_kernel(const __half* __restrict__ q, const __half* __restrict__ k,
                        const float* __restrict__ off, __half* __restrict__ outop) {
    const int gwarp = (blockIdx.x * blockDim.x + threadIdx.x) >> 5;
    const int lane = threadIdx.x & 31;
    if (gwarp >= MM * NHEADS) return;

    const int h = gwarp & (NHEADS - 1);
    const int m = gwarp >> 3;
    const int n = m % NN;
    const int b = m / NN;

    const int ch = h * HD + lane * 4;
    const __half2* qp = reinterpret_cast<const __half2*>(q + (size_t)m * CC + ch);
    float2 q01 = __half22float2(qp[0]), q23 = __half22float2(qp[1]);
    float4 qv = make_float4(q01.x, q01.y, q23.x, q23.y);

    const int iy_n = n / WW;
    const int ix_n = n % WW;
    const float cy = -1.0f + 2.0f * (float)iy_n / (float)(HH - 1);
    const float cx = -1.0f + 2.0f * (float)ix_n / (float)(WW - 1);

    const float* offp = off + (size_t)m * 128 + h * (NPTS * 2);
    const __half* kb = k + (size_t)b * NN * CC;

    float sk[NPTS][4];
    float score[NPTS];
    const float scale = 0.08838834764831845f;

#pragma unroll
    for (int p = 0; p < NPTS; p++) {
        float l0 = cy + offp[2 * p + 0];
        float l1 = cx + offp[2 * p + 1];
        float ix = (l0 + 1.0f) * 0.5f * (float)(WW - 1);
        float iy = (l1 + 1.0f) * 0.5f * (float)(HH - 1);
        ix = fminf(fmaxf(ix, 0.0f), (float)(WW - 1));
        iy = fminf(fmaxf(iy, 0.0f), (float)(HH - 1));
        float x0f = floorf(ix), y0f = floorf(iy);
        float wx = ix - x0f, wy = iy - y0f;
        int x0 = (int)x0f, y0 = (int)y0f;
        int x1 = min(x0 + 1, WW - 1);
        int y1 = min(y0 + 1, HH - 1);

        const __half2* p00 = reinterpret_cast<const __half2*>(kb + (size_t)(y0 * WW + x0) * CC + ch);
        const __half2* p01 = reinterpret_cast<const __half2*>(kb + (size_t)(y0 * WW + x1) * CC + ch);
        const __half2* p10 = reinterpret_cast<const __half2*>(kb + (size_t)(y1 * WW + x0) * CC + ch);
        const __half2* p11 = reinterpret_cast<const __half2*>(kb + (size_t)(y1 * WW + x1) * CC + ch);
        float2 a00 = __half22float2(p00[0]), b00 = __half22float2(p00[1]);
        float2 a01 = __half22float2(p01[0]), b01 = __half22float2(p01[1]);
        float2 a10 = __half22float2(p10[0]), b10 = __half22float2(p10[1]);
        float2 a11 = __half22float2(p11[0]), b11 = __half22float2(p11[1]);

        float w00 = (1.0f - wy) * (1.0f - wx);
        float w01 = (1.0f - wy) * wx;
        float w10 = wy * (1.0f - wx);
        float w11 = wy * wx;

        sk[p][0] = a00.x * w00 + a01.x * w01 + a10.x * w10 + a11.x * w11;
        sk[p][1] = a00.y * w00 + a01.y * w01 + a10.y * w10 + a11.y * w11;
        sk[p][2] = b00.x * w00 + b01.x * w01 + b10.x * w10 + b11.x * w11;
        sk[p][3] = b00.y * w00 + b01.y * w01 + b10.y * w10 + b11.y * w11;

        float s = qv.x * sk[p][0] + qv.y * sk[p][1] + qv.z * sk[p][2] + qv.w * sk[p][3];
#pragma unroll
        for (int d = 16; d > 0; d >>= 1)
            s += __shfl_xor_sync(0xFFFFFFFFu, s, d);
        score[p] = s * scale;
    }

    float mx = score[0];
#pragma unroll
    for (int p = 1; p < NPTS; p++) mx = fmaxf(mx, score[p]);
    float denom = 0.0f;
    float e[NPTS];
#pragma unroll
    for (int p = 0; p < NPTS; p++) { e[p] = __expf(score[p] - mx); denom += e[p]; }
    float inv = 1.0f / denom;

    float av[4] = {0.f, 0.f, 0.f, 0.f};
#pragma unroll
    for (int p = 0; p < NPTS; p++) {
        float a = e[p] * inv;
        av[0] += a * sk[p][0];
        av[1] += a * sk[p][1];
        av[2] += a * sk[p][2];
        av[3] += a * sk[p][3];
    }

    __half hi[4];
#pragma unroll
    for (int j = 0; j < 4; j++) hi[j] = __float2half(av[j]);
    __half* rp = outop + (size_t)m * K1;
    *reinterpret_cast<uint2*>(rp + ch) = *reinterpret_cast<uint2*>(hi);
}

// ---------------------------------------------------------------------------
extern "C" void kernel_launch(void* const* d_in, const int* in_sizes, int n_in,
                              void* d_out, int out_size) {
    const float* query = (const float*)d_in[0];
    const float* ref   = (const float*)d_in[1];
    const float* Wq    = (const float*)d_in[2];
    const float* bq    = (const float*)d_in[3];
    const float* Wkv   = (const float*)d_in[4];
    const float* bkv   = (const float*)d_in[5];
    const float* Woff  = (const float*)d_in[6];
    const float* boff  = (const float*)d_in[7];
    const float* Wout  = (const float*)d_in[8];
    const float* bout  = (const float*)d_in[9];
    float* outp = (float*)d_out;

    __half *aq, *ak, *bq_op, *bk_op, *bo_op, *bf_op, *qb, *kb;
    float *offp;
    cudaGetSymbolAddress((void**)&aq,    g_aq);
    cudaGetSymbolAddress((void**)&ak,    g_ak);
    cudaGetSymbolAddress((void**)&bq_op, g_bop_q);
    cudaGetSymbolAddress((void**)&bk_op, g_bop_k);
    cudaGetSymbolAddress((void**)&bo_op, g_bop_o);
    cudaGetSymbolAddress((void**)&bf_op, g_bop_f);
    cudaGetSymbolAddress((void**)&qb,    g_q);
    cudaGetSymbolAddress((void**)&kb,    g_k);
    cudaGetSymbolAddress((void**)&offp,  g_offp);

    cudaFuncSetAttribute(gemm3, cudaFuncAttributeMaxDynamicSharedMemorySize, SMEM_SZ);
    cudaFuncSetAttribute(gemm_out, cudaFuncAttributeMaxDynamicSharedMemorySize, SMEM_SZ);

    // 1. ALL conversions (weights + both activations) in one launch
    conv_all<<<4096 + 2 * ACT_BLKS, 256>>>(Wq, Wkv, Wout, Woff,
                                           bq_op, bk_op, bo_op, bf_op,
                                           query, ref, aq, ak);

    // 2. off (K3) + q (K1, fp16 out) + k (K1, fp16 out) in one launch
    gemm3<<<17 * MTILES, 256, SMEM_SZ>>>(aq, ak, bq_op, bk_op, bf_op,
                                         bq, bkv, boff, qb, kb, offp);

    // 3. sampling + attention; writes fp16 [Ah] attn operand into ak (reuse)
    {
        int warps = MM * NHEADS;
        int blocks = (warps * 32 + 255) / 256;
        sample_attn_kernel<<<blocks, 256>>>(qb, kb, offp, ak);
    }

    // 4. out = attn @ Wout + bout  (K1)
    gemm_out<<<dim3(8, MTILES), 256, SMEM_SZ>>>(ak, bo_op, bout, outp);
}

// round 10
// speedup vs baseline: 2.8082x; 1.0152x over previous
#include <cuda_runtime.h>
#include <cuda_fp16.h>
#include <math.h>
#include <cstdint>

// Problem constants
#define BB 8
#define HH 37
#define WW 37
#define NN (HH * WW)          // 1369
#define CC 1024
#define MM (BB * NN)          // 10952
#define NHEADS 8
#define HD 128
#define NPTS 8
#define K1 1024               // 1-term fp16 (q, k, out GEMMs)
#define K2 2048               // [Ah|Al] activation layout (off GEMM aliases term2 -> term0)
#define K3 3072               // off GEMM logical K (B = [Bh|Bh|Bl])
#define NCK1 (K1 / 64)        // 16
#define NCK3 (K3 / 64)        // 48
#define STAGES 3
#define STAGE_BYTES 32768     // A 16K + B 16K
#define SMEM_SZ (STAGES * STAGE_BYTES)
#define MTILES 86             // ceil(MM/128)
#define ACT_BLKS 5476         // MM*128/256

// ---------------------------------------------------------------------------
// Scratch
// ---------------------------------------------------------------------------
__device__ __half g_aq[MM * K2];      // query [Ah|Al] (q uses K1 prefix, off aliases chunks)
__device__ __half g_ak[MM * K1];      // ref [Ah]; reused as attn [Ah]
__device__ __half g_bop_q[CC * K1];   // Wq [Bh]
__device__ __half g_bop_k[CC * K1];   // Wkv[:, :C] [Bh]
__device__ __half g_bop_o[CC * K1];   // Wout [Bh]
__device__ __half g_bop_f[128 * K3];  // Woff [Bh|Bh|Bl]
__device__ __half g_q[MM * CC];       // q in fp16
__device__ __half g_k[MM * CC];       // k in fp16
__device__ float  g_offp[MM * 128];

// ---------------------------------------------------------------------------
__device__ __forceinline__ uint32_t smem_u32(const void* p) {
    uint32_t a;
    asm("{ .reg .u64 t; cvta.to.shared.u64 t, %1; cvt.u32.u64 %0, t; }" : "=r"(a) : "l"(p));
    return a;
}
__device__ __forceinline__ void cp16(uint32_t dst, const void* src, bool valid) {
    int sz = valid ? 16 : 0;
    asm volatile("cp.async.cg.shared.global [%0], [%1], 16, %2;"
                 :: "r"(dst), "l"(src), "r"(sz) : "memory");
}
#define CP_COMMIT() asm volatile("cp.async.commit_group;" ::: "memory")
#define CP_WAIT1()  asm volatile("cp.async.wait_group 1;" ::: "memory")

__device__ __forceinline__ void ldsm4(uint32_t* r, uint32_t addr) {
    asm volatile("ldmatrix.sync.aligned.m8n8.x4.shared.b16 {%0,%1,%2,%3}, [%4];"
                 : "=r"(r[0]), "=r"(r[1]), "=r"(r[2]), "=r"(r[3]) : "r"(addr));
}
__device__ __forceinline__ void mma16816(float* c, const uint32_t* a, const uint32_t* b) {
    asm volatile(
        "mma.sync.aligned.m16n8k16.row.col.f32.f16.f16.f32 "
        "{%0,%1,%2,%3},{%4,%5,%6,%7},{%8,%9},{%0,%1,%2,%3};"
        : "+f"(c[0]), "+f"(c[1]), "+f"(c[2]), "+f"(c[3])
        : "r"(a[0]), "r"(a[1]), "r"(a[2]), "r"(a[3]), "r"(b[0]), "r"(b[1]));
}

// ---------------------------------------------------------------------------
// GEMM body: CTA 128x128, 8 warps 64x32, 3-stage cp.async, ONE sync per chunk.
// ka_wrap: A-chunk aliasing (off GEMM: chunk c>=32 reads chunk c-32).
// ---------------------------------------------------------------------------
template <typename OutT>
__device__ __forceinline__
void gemm_body(const __half* __restrict__ A, int lda,
               const __half* __restrict__ B, int ldb,
               const float* __restrict__ bias, OutT* __restrict__ C,
               int ldc, int m0, int col0, int nchunk, int ka_wrap, char* smem) {
    const uint32_t sb0 = smem_u32(smem);
    const int tid = threadIdx.x, wid = tid >> 5, lane = tid & 31;
    const __half* Bc0 = B + (size_t)col0 * ldb;

    auto load_stage = [&](int ck, int stage) {
        const uint32_t sa = sb0 + stage * STAGE_BYTES;
        const int ca = (ck >= ka_wrap) ? ck - ka_wrap : ck;
        const __half* Ac = A + ca * 64;
        const __half* Bc = Bc0 + ck * 64;
#pragma unroll
        for (int i = 0; i < 4; i++) {
            int id = tid + i * 256;
            int row = id >> 3, c16 = id & 7;
            int gr = m0 + row;
            bool v = gr < MM;
            int grc = v ? gr : (MM - 1);
            uint32_t dst = sa + row * 128 + (((uint32_t)c16 ^ (row & 7)) << 4);
            cp16(dst, Ac + (size_t)grc * lda + c16 * 8, v);
        }
#pragma unroll
        for (int i = 0; i < 4; i++) {
            int id = tid + i * 256;
            int row = id >> 3, c16 = id & 7;
            uint32_t dst = sa + 16384 + row * 128 + (((uint32_t)c16 ^ (row & 7)) << 4);
            cp16(dst, Bc + (size_t)row * ldb + c16 * 8, true);
        }
        CP_COMMIT();
    };

    float acc[4][4][4];
#pragma unroll
    for (int mt = 0; mt < 4; mt++)
#pragma unroll
        for (int nt = 0; nt < 4; nt++)
#pragma unroll
            for (int j = 0; j < 4; j++) acc[mt][nt][j] = 0.0f;

    load_stage(0, 0);
    load_stage(1, 1);

    const int wm = (wid & 1) * 64;
    const int wn = (wid >> 1) * 32;

    for (int c = 0; c < nchunk; c++) {
        CP_WAIT1();
        __syncthreads();   // single barrier: also protects buffer reuse (stage c+3 == buffer c%3)
        if (c + 2 < nchunk) load_stage(c + 2, (c + 2) % STAGES);
        else CP_COMMIT();

        const uint32_t sa = sb0 + (c % STAGES) * STAGE_BYTES;
        const uint32_t sbB = sa + 16384;

#pragma unroll
        for (int ks = 0; ks < 4; ks++) {
            uint32_t af[4][4];
#pragma unroll
            for (int mt = 0; mt < 4; mt++) {
                int row = wm + mt * 16 + (lane & 15);
                uint32_t c16 = (uint32_t)(ks * 2 + (lane >> 4)) ^ (row & 7);
                ldsm4(af[mt], sa + row * 128 + (c16 << 4));
            }
            uint32_t bf[4][2];
#pragma unroll
            for (int nt2 = 0; nt2 < 2; nt2++) {
                int group = lane >> 3;
                int nrow = wn + nt2 * 16 + (group >> 1) * 8 + (lane & 7);
                uint32_t c16 = (uint32_t)(ks * 2 + (group & 1)) ^ (nrow & 7);
                uint32_t r[4];
                ldsm4(r, sbB + nrow * 128 + (c16 << 4));
                bf[nt2 * 2][0] = r[0]; bf[nt2 * 2][1] = r[1];
                bf[nt2 * 2 + 1][0] = r[2]; bf[nt2 * 2 + 1][1] = r[3];
            }
#pragma unroll
            for (int mt = 0; mt < 4; mt++)
#pragma unroll
                for (int nt = 0; nt < 4; nt++)
                    mma16816(acc[mt][nt], af[mt], bf[nt]);
        }
    }
    __syncthreads();   // before epilogue (smem not reused, but cheap and keeps warps together)

    const int lr = lane >> 2, lc = (lane & 3) * 2;
#pragma unroll
    for (int mt = 0; mt < 4; mt++) {
#pragma unroll
        for (int nt = 0; nt < 4; nt++) {
            int r0 = m0 + wm + mt * 16 + lr;
            int cb = col0 + wn + nt * 8 + lc;
            float b0 = bias[cb], b1 = bias[cb + 1];
            if (r0 < MM) {
                if (sizeof(OutT) == 2) {
                    __half2 v = __floats2half2_rn(acc[mt][nt][0] + b0, acc[mt][nt][1] + b1);
                    *reinterpret_cast<__half2*>((__half*)C + (size_t)r0 * ldc + cb) = v;
                } else {
                    float2 v = make_float2(acc[mt][nt][0] + b0, acc[mt][nt][1] + b1);
                    *reinterpret_cast<float2*>((float*)C + (size_t)r0 * ldc + cb) = v;
                }
            }
            int r1 = r0 + 8;
            if (r1 < MM) {
                if (sizeof(OutT) == 2) {
                    __half2 v = __floats2half2_rn(acc[mt][nt][2] + b0, acc[mt][nt][3] + b1);
                    *reinterpret_cast<__half2*>((__half*)C + (size_t)r1 * ldc + cb) = v;
                } else {
                    float2 v = make_float2(acc[mt][nt][2] + b0, acc[mt][nt][3] + b1);
                    *reinterpret_cast<float2*>((float*)C + (size_t)r1 * ldc + cb) = v;
                }
            }
        }
    }
}

// Merged off + q + k GEMM. t = bx / MTILES:
// t == 0: off (K3 logical, A aliased mod 32); t in [1,9): q; t in [9,17): k.
__global__ __launch_bounds__(256)
void gemm3(const __half* __restrict__ Aq, const __half* __restrict__ Ak,
           const __half* __restrict__ Bq, const __half* __restrict__ Bk,
           const __half* __restrict__ Bf,
           const float* __restrict__ bq, const float* __restrict__ bkv,
           const float* __restrict__ boff,
           __half* __restrict__ Cq, __half* __restrict__ Ck, float* __restrict__ Coff) {
    extern __shared__ char smem[];
    const int bx = blockIdx.x;
    const int t = bx / MTILES;
    const int m0 = (bx % MTILES) * 128;
    if (t == 0) {
        gemm_body<float>(Aq, K2, Bf, K3, boff, Coff, 128, m0, 0, NCK3, 32, smem);
    } else if (t < 9) {
        gemm_body<__half>(Aq, K2, Bq, K1, bq, Cq, CC, m0, (t - 1) * 128, NCK1, 9999, smem);
    } else {
        gemm_body<__half>(Ak, K1, Bk, K1, bkv, Ck, CC, m0, (t - 9) * 128, NCK1, 9999, smem);
    }
}

// Final GEMM: out = attn(K1) @ Wout + bout
__global__ __launch_bounds__(256)
void gemm_out(const __half* __restrict__ A, const __half* __restrict__ B,
              const float* __restrict__ bias, float* __restrict__ C) {
    extern __shared__ char smem[];
    gemm_body<float>(A, K1, B, K1, bias, C, CC, blockIdx.y * 128, blockIdx.x * 128,
                     NCK1, 9999, smem);
}

// ---------------------------------------------------------------------------
// ALL conversions in one launch. Grid = 4096 (weights) + 2*ACT_BLKS (acts).
// ---------------------------------------------------------------------------
__global__ __launch_bounds__(256)
void conv_all(const float* __restrict__ Wq, const float* __restrict__ Wkv,
              const float* __restrict__ Wout, const float* __restrict__ Woff,
              __half* __restrict__ Oq, __half* __restrict__ Ok,
              __half* __restrict__ Oo, __half* __restrict__ Of,
              const float* __restrict__ query, const float* __restrict__ ref,
              __half* __restrict__ aq, __half* __restrict__ ak) {
    const int bid = blockIdx.x;
    if (bid < 4096) {
        const int z = bid >> 10, r = bid & 1023;
        const int nt = r & 31, kt = r >> 5;
        if (z == 3 && nt >= 4) return;
        const float* W;
        int ldw, nvalid;
        if (z == 0)      { W = Wq;   ldw = CC;     nvalid = CC; }
        else if (z == 1) { W = Wkv;  ldw = 2 * CC; nvalid = CC; }
        else if (z == 2) { W = Wout; ldw = CC;     nvalid = CC; }
        else             { W = Woff; ldw = 128;    nvalid = 128; }

        __shared__ float t[32][33];
        const int tx = threadIdx.x & 31, ty = threadIdx.x >> 5;
        const int n0 = nt * 32, k0 = kt * 32;
#pragma unroll
        for (int j = ty; j < 32; j += 8) {
            int n = n0 + tx, k = k0 + j;
            t[j][tx] = (n < nvalid) ? W[(size_t)k * ldw + n] : 0.0f;
        }
        __syncthreads();
#pragma unroll
        for (int j = ty; j < 32; j += 8) {
            int n = n0 + j, k = k0 + tx;
            float v = t[tx][j];
            __half h = __float2half(v);
            if (z == 0)      { Oq[(size_t)n * K1 + k] = h; }
            else if (z == 1) { Ok[(size_t)n * K1 + k] = h; }
            else if (z == 2) { Oo[(size_t)n * K1 + k] = h; }
            else             { __half l = __float2half(v - __half2float(h));
                               __half* row = Of + (size_t)n * K3;
                               row[k] = h; row[k + 1024] = h; row[k + 2048] = l; }
        }
    } else {
        const int j = bid - 4096;
        const bool isq = j < ACT_BLKS;
        const int blk = isq ? j : j - ACT_BLKS;
        size_t i = (size_t)blk * 256 + threadIdx.x;
        if (i >= (size_t)MM * 128) return;
        size_t rrow = i >> 7;
        int c8 = (int)(i & 127) * 8;
        const float* A = isq ? query : ref;
        const float4* p = reinterpret_cast<const float4*>(A + rrow * CC + c8);
        float4 v0 = p[0], v1 = p[1];
        float vv[8] = {v0.x, v0.y, v0.z, v0.w, v1.x, v1.y, v1.z, v1.w};
        __half hi[8], lo[8];
#pragma unroll
        for (int jj = 0; jj < 8; jj++) {
            hi[jj] = __float2half(vv[jj]);
            lo[jj] = __float2half(vv[jj] - __half2float(hi[jj]));
        }
        if (isq) {  // query: [Ah|Al] stride K2 (off GEMM aliases term2 -> Ah region)
            __half* rp = aq + rrow * K2;
            *reinterpret_cast<uint4*>(rp + c8)        = *reinterpret_cast<uint4*>(hi);
            *reinterpret_cast<uint4*>(rp + c8 + 1024) = *reinterpret_cast<uint4*>(lo);
        } else {    // ref: [Ah] stride K1
            __half* rp = ak + rrow * K1;
            *reinterpret_cast<uint4*>(rp + c8) = *reinterpret_cast<uint4*>(hi);
        }
    }
}

// ---------------------------------------------------------------------------
// Sampling + attention. One warp per (b, n, head). q, k fp16.
// Writes fp16 attn operand [Ah] (stride K1) directly.
// ---------------------------------------------------------------------------
__global__ __launch_bounds__(256)
void sample_attn_kernel(const __half* __restrict__ q, const __half* __restrict__ k,
                        const float* __restrict__ off, __half* __restrict__ outop) {
    const int gwarp = (blockIdx.x * blockDim.x + threadIdx.x) >> 5;
    const int lane = threadIdx.x & 31;
    if (gwarp >= MM * NHEADS) return;

    const int h = gwarp & (NHEADS - 1);
    const int m = gwarp >> 3;
    const int n = m % NN;
    const int b = m / NN;

    const int ch = h * HD + lane * 4;
    const __half2* qp = reinterpret_cast<const __half2*>(q + (size_t)m * CC + ch);
    float2 q01 = __half22float2(qp[0]), q23 = __half22float2(qp[1]);
    float4 qv = make_float4(q01.x, q01.y, q23.x, q23.y);

    const int iy_n = n / WW;
    const int ix_n = n % WW;
    const float cy = -1.0f + 2.0f * (float)iy_n / (float)(HH - 1);
    const float cx = -1.0f + 2.0f * (float)ix_n / (float)(WW - 1);

    const float* offp = off + (size_t)m * 128 + h * (NPTS * 2);
    const __half* kb = k + (size_t)b * NN * CC;

    float sk[NPTS][4];
    float score[NPTS];
    const float scale = 0.08838834764831845f;

#pragma unroll
    for (int p = 0; p < NPTS; p++) {
        float l0 = cy + offp[2 * p + 0];
        float l1 = cx + offp[2 * p + 1];
        float ix = (l0 + 1.0f) * 0.5f * (float)(WW - 1);
        float iy = (l1 + 1.0f) * 0.5f * (float)(HH - 1);
        ix = fminf(fmaxf(ix, 0.0f), (float)(WW - 1));
        iy = fminf(fmaxf(iy, 0.0f), (float)(HH - 1));
        float x0f = floorf(ix), y0f = floorf(iy);
        float wx = ix - x0f, wy = iy - y0f;
        int x0 = (int)x0f, y0 = (int)y0f;
        int x1 = min(x0 + 1, WW - 1);
        int y1 = min(y0 + 1, HH - 1);

        const __half2* p00 = reinterpret_cast<const __half2*>(kb + (size_t)(y0 * WW + x0) * CC + ch);
        const __half2* p01 = reinterpret_cast<const __half2*>(kb + (size_t)(y0 * WW + x1) * CC + ch);
        const __half2* p10 = reinterpret_cast<const __half2*>(kb + (size_t)(y1 * WW + x0) * CC + ch);
        const __half2* p11 = reinterpret_cast<const __half2*>(kb + (size_t)(y1 * WW + x1) * CC + ch);
        float2 a00 = __half22float2(p00[0]), b00 = __half22float2(p00[1]);
        float2 a01 = __half22float2(p01[0]), b01 = __half22float2(p01[1]);
        float2 a10 = __half22float2(p10[0]), b10 = __half22float2(p10[1]);
        float2 a11 = __half22float2(p11[0]), b11 = __half22float2(p11[1]);

        float w00 = (1.0f - wy) * (1.0f - wx);
        float w01 = (1.0f - wy) * wx;
        float w10 = wy * (1.0f - wx);
        float w11 = wy * wx;

        sk[p][0] = a00.x * w00 + a01.x * w01 + a10.x * w10 + a11.x * w11;
        sk[p][1] = a00.y * w00 + a01.y * w01 + a10.y * w10 + a11.y * w11;
        sk[p][2] = b00.x * w00 + b01.x * w01 + b10.x * w10 + b11.x * w11;
        sk[p][3] = b00.y * w00 + b01.y * w01 + b10.y * w10 + b11.y * w11;

        float s = qv.x * sk[p][0] + qv.y * sk[p][1] + qv.z * sk[p][2] + qv.w * sk[p][3];
#pragma unroll
        for (int d = 16; d > 0; d >>= 1)
            s += __shfl_xor_sync(0xFFFFFFFFu, s, d);
        score[p] = s * scale;
    }

    float mx = score[0];
#pragma unroll
    for (int p = 1; p < NPTS; p++) mx = fmaxf(mx, score[p]);
    float denom = 0.0f;
    float e[NPTS];
#pragma unroll
    for (int p = 0; p < NPTS; p++) { e[p] = __expf(score[p] - mx); denom += e[p]; }
    float inv = 1.0f / denom;

    float av[4] = {0.f, 0.f, 0.f, 0.f};
#pragma unroll
    for (int p = 0; p < NPTS; p++) {
        float a = e[p] * inv;
        av[0] += a * sk[p][0];
        av[1] += a * sk[p][1];
        av[2] += a * sk[p][2];
        av[3] += a * sk[p][3];
    }

    __half hi[4];
#pragma unroll
    for (int j = 0; j < 4; j++) hi[j] = __float2half(av[j]);
    __half* rp = outop + (size_t)m * K1;
    *reinterpret_cast<uint2*>(rp + ch) = *reinterpret_cast<uint2*>(hi);
}

// ---------------------------------------------------------------------------
extern "C" void kernel_launch(void* const* d_in, const int* in_sizes, int n_in,
                              void* d_out, int out_size) {
    const float* query = (const float*)d_in[0];
    const float* ref   = (const float*)d_in[1];
    const float* Wq    = (const float*)d_in[2];
    const float* bq    = (const float*)d_in[3];
    const float* Wkv   = (const float*)d_in[4];
    const float* bkv   = (const float*)d_in[5];
    const float* Woff  = (const float*)d_in[6];
    const float* boff  = (const float*)d_in[7];
    const float* Wout  = (const float*)d_in[8];
    const float* bout  = (const float*)d_in[9];
    float* outp = (float*)d_out;

    __half *aq, *ak, *bq_op, *bk_op, *bo_op, *bf_op, *qb, *kb;
    float *offp;
    cudaGetSymbolAddress((void**)&aq,    g_aq);
    cudaGetSymbolAddress((void**)&ak,    g_ak);
    cudaGetSymbolAddress((void**)&bq_op, g_bop_q);
    cudaGetSymbolAddress((void**)&bk_op, g_bop_k);
    cudaGetSymbolAddress((void**)&bo_op, g_bop_o);
    cudaGetSymbolAddress((void**)&bf_op, g_bop_f);
    cudaGetSymbolAddress((void**)&qb,    g_q);
    cudaGetSymbolAddress((void**)&kb,    g_k);
    cudaGetSymbolAddress((void**)&offp,  g_offp);

    cudaFuncSetAttribute(gemm3, cudaFuncAttributeMaxDynamicSharedMemorySize, SMEM_SZ);
    cudaFuncSetAttribute(gemm_out, cudaFuncAttributeMaxDynamicSharedMemorySize, SMEM_SZ);

    // 1. ALL conversions (weights + both activations) in one launch
    conv_all<<<4096 + 2 * ACT_BLKS, 256>>>(Wq, Wkv, Wout, Woff,
                                           bq_op, bk_op, bo_op, bf_op,
                                           query, ref, aq, ak);

    // 2. off (K3, A aliased) + q (K1) + k (K1) in one launch
    gemm3<<<17 * MTILES, 256, SMEM_SZ>>>(aq, ak, bq_op, bk_op, bf_op,
                                         bq, bkv, boff, qb, kb, offp);

    // 3. sampling + attention; writes fp16 [Ah] attn operand into ak (reuse)
    {
        int warps = MM * NHEADS;
        int blocks = (warps * 32 + 255) / 256;
        sample_attn_kernel<<<blocks, 256>>>(qb, kb, offp, ak);
    }

    // 4. out = attn @ Wout + bout  (K1)
    gemm_out<<<dim3(8, MTILES), 256, SMEM_SZ>>>(ak, bo_op, bout, outp);
}